// round 9
// baseline (speedup 1.0000x reference)
#include <cuda_runtime.h>
#include <cuda_bf16.h>
#include <math.h>

#define BB 2
#define SS 2048
#define DD 1024
#define NH 16
#define NKV 4
#define QKB 16
#define VB 32
#define NREP (NH / NKV)
#define MROWS (BB * SS)       // 4096
#define NQKV (NH * QKB + NKV * QKB + NKV * VB)   // 448
#define KO (NH * VB)          // 512

typedef unsigned int u32;
typedef unsigned short u16;

// ---- bf16 split helpers ----
__device__ __forceinline__ void bsplit(float x, float& hi, float& lo) {
    float h = __bfloat162float(__float2bfloat16(x));
    hi = h; lo = x - h;
}
__device__ __forceinline__ u32 packbf2(float a, float b) {   // a -> low half
    __nv_bfloat162 t = __floats2bfloat162_rn(a, b);
    return *(u32*)&t;
}

// ---- mma.sync m16n8k16 bf16, f32 accum (fragment mappings verified R6) ----
__device__ __forceinline__ void mma16816(float c[4], const u32 a[4], const u32 b[2]) {
    asm volatile(
        "mma.sync.aligned.m16n8k16.row.col.f32.bf16.bf16.f32 "
        "{%0,%1,%2,%3}, {%4,%5,%6,%7}, {%8,%9}, {%0,%1,%2,%3};"
        : "+f"(c[0]), "+f"(c[1]), "+f"(c[2]), "+f"(c[3])
        : "r"(a[0]), "r"(a[1]), "r"(a[2]), "r"(a[3]), "r"(b[0]), "r"(b[1]));
}

// ---- scratch (__device__ globals; no allocation allowed) ----
__device__ __align__(16) u16 g_hsh[MROWS * DD];
__device__ __align__(16) u16 g_hsl[MROWS * DD];
__device__ __align__(16) u16 g_wth[NQKV * DD];
__device__ __align__(16) u16 g_wtl[NQKV * DD];
__device__ __align__(16) u16 g_woth[DD * KO];
__device__ __align__(16) u16 g_wotl[DD * KO];
__device__ __align__(16) float g_qkv[MROWS * NQKV];
__device__ __align__(16) u16 g_ovhh[MROWS * KO];
__device__ __align__(16) u16 g_ovhl[MROWS * KO];
__device__ __align__(16) u16 g_qmh[BB * NH * SS * QKB];
__device__ __align__(16) u16 g_qml[BB * NH * SS * QKB];
__device__ __align__(16) float g_qc[BB * NH * SS];
__device__ __align__(16) u16 g_kh[BB * NKV * SS * QKB];
__device__ __align__(16) u16 g_kl[BB * NKV * SS * QKB];
__device__ __align__(16) u16 g_vth[BB * NKV * VB * SS];
__device__ __align__(16) u16 g_vtl[BB * NKV * VB * SS];

// ---------------------------------------------------------------------------
// Elementwise fp32 -> split bf16 (hi/lo). 8 elems/thread, all float4.
// ---------------------------------------------------------------------------
__global__ void convert_split_kernel(const float* __restrict__ src,
                                     u16* __restrict__ dh, u16* __restrict__ dl,
                                     int total)
{
    int idx = blockIdx.x * blockDim.x + threadIdx.x;
    int base = idx * 8;
    if (base >= total) return;
    float4 v0 = *(const float4*)(src + base);
    float4 v1 = *(const float4*)(src + base + 4);
    float xs[8] = {v0.x, v0.y, v0.z, v0.w, v1.x, v1.y, v1.z, v1.w};
    __align__(16) u32 oh[4];
    __align__(16) u32 ol[4];
#pragma unroll
    for (int i = 0; i < 4; i++) {
        float h0, l0, h1, l1;
        bsplit(xs[2 * i], h0, l0);
        bsplit(xs[2 * i + 1], h1, l1);
        oh[i] = packbf2(h0, h1);
        ol[i] = packbf2(l0, l1);
    }
    *(float4*)(dh + base) = *(float4*)&oh[0];
    *(float4*)(dl + base) = *(float4*)&ol[0];
}

// ---------------------------------------------------------------------------
// Transpose + split a weight: src fp32 [K][N] -> dst bf16 [nOff+n][K].
// ---------------------------------------------------------------------------
__global__ void __launch_bounds__(256) transpose_split_kernel(
    const float* __restrict__ src, int K, int N,
    u16* __restrict__ dh, u16* __restrict__ dl, int dstStride, int nOff)
{
    __shared__ __align__(16) float tile[32][33];
    const int n0 = blockIdx.x * 32;
    const int k0 = blockIdx.y * 32;
    const int t = threadIdx.x;
    {
        int r = t >> 3, c = (t & 7) * 4;
        float4 v = *(const float4*)(src + (size_t)(k0 + r) * N + n0 + c);
        tile[r][c + 0] = v.x; tile[r][c + 1] = v.y;
        tile[r][c + 2] = v.z; tile[r][c + 3] = v.w;
    }
    __syncthreads();
    {
        int col = t >> 3, k4 = (t & 7) * 4;
        __align__(8) u32 oh[2];
        __align__(8) u32 ol[2];
#pragma unroll
        for (int i = 0; i < 2; i++) {
            float h0, l0, h1, l1;
            bsplit(tile[k4 + 2 * i][col], h0, l0);
            bsplit(tile[k4 + 2 * i + 1][col], h1, l1);
            oh[i] = packbf2(h0, h1);
            ol[i] = packbf2(l0, l1);
        }
        size_t o = (size_t)(nOff + n0 + col) * dstStride + k0 + k4;
        *(float2*)(dh + o) = *(float2*)&oh[0];
        *(float2*)(dl + o) = *(float2*)&ol[0];
    }
}

// ---------------------------------------------------------------------------
// Split-bf16 tensor-core GEMM: C[M,N] = A[M,K] @ B^T (B stored [N][K]).
// Tile 128x64x32, 256 threads, warp tile 32x32, 3 MMAs per product.
// Register-prefetch software pipeline: fetch tile k+32 during compute of k.
// ---------------------------------------------------------------------------
template <int SIG>
__global__ void __launch_bounds__(256) bgemm_kernel(
    const u16* __restrict__ Ah, const u16* __restrict__ Al,
    const u16* __restrict__ Bh, const u16* __restrict__ Bl,
    float* __restrict__ C, int M, int N, int K)
{
    __shared__ __align__(16) u16 sAh[128][40];
    __shared__ __align__(16) u16 sAl[128][40];
    __shared__ __align__(16) u16 sBh[64][40];
    __shared__ __align__(16) u16 sBl[64][40];

    const int tid = threadIdx.x, warp = tid >> 5, lane = tid & 31;
    const int g = lane >> 2, tg = lane & 3;
    const int wm = warp >> 1, wn = warp & 1;
    const int row0 = blockIdx.y * 128, col0 = blockIdx.x * 64;

    // per-thread load coordinates
    const int ar0 = tid >> 2,          ac0 = (tid & 3) * 8;          // A chunk 0
    const int ar1 = (tid + 256) >> 2,  ac1 = ((tid + 256) & 3) * 8;  // A chunk 1
    const int br  = tid >> 2,          bc  = (tid & 3) * 8;          // B chunk

    float4 pAh0, pAl0, pAh1, pAl1, pBh, pBl;

    #define BG_FETCH(k0_) do {                                                      \
        pAh0 = *(const float4*)(Ah + (size_t)(row0 + ar0) * K + (k0_) + ac0);       \
        pAl0 = *(const float4*)(Al + (size_t)(row0 + ar0) * K + (k0_) + ac0);       \
        pAh1 = *(const float4*)(Ah + (size_t)(row0 + ar1) * K + (k0_) + ac1);       \
        pAl1 = *(const float4*)(Al + (size_t)(row0 + ar1) * K + (k0_) + ac1);       \
        pBh  = *(const float4*)(Bh + (size_t)(col0 + br) * K + (k0_) + bc);         \
        pBl  = *(const float4*)(Bl + (size_t)(col0 + br) * K + (k0_) + bc);         \
    } while (0)

    #define BG_STORE() do {                                                         \
        *(float4*)&sAh[ar0][ac0] = pAh0;  *(float4*)&sAl[ar0][ac0] = pAl0;          \
        *(float4*)&sAh[ar1][ac1] = pAh1;  *(float4*)&sAl[ar1][ac1] = pAl1;          \
        *(float4*)&sBh[br][bc]   = pBh;   *(float4*)&sBl[br][bc]   = pBl;           \
    } while (0)

    float acc[2][4][4];
#pragma unroll
    for (int mt = 0; mt < 2; mt++)
#pragma unroll
        for (int nt = 0; nt < 4; nt++)
#pragma unroll
            for (int i = 0; i < 4; i++) acc[mt][nt][i] = 0.f;

    BG_FETCH(0);
    BG_STORE();
    __syncthreads();

    for (int k0 = 0; k0 < K; k0 += 32) {
        const bool more = (k0 + 32) < K;
        if (more) BG_FETCH(k0 + 32);

#pragma unroll
        for (int k16 = 0; k16 < 2; k16++) {
            const int kb = k16 * 16 + tg * 2;
            u32 ah[2][4], al[2][4];
#pragma unroll
            for (int mt = 0; mt < 2; mt++) {
                int ar = wm * 32 + mt * 16 + g;
                ah[mt][0] = *(const u32*)&sAh[ar][kb];
                ah[mt][1] = *(const u32*)&sAh[ar + 8][kb];
                ah[mt][2] = *(const u32*)&sAh[ar][kb + 8];
                ah[mt][3] = *(const u32*)&sAh[ar + 8][kb + 8];
                al[mt][0] = *(const u32*)&sAl[ar][kb];
                al[mt][1] = *(const u32*)&sAl[ar + 8][kb];
                al[mt][2] = *(const u32*)&sAl[ar][kb + 8];
                al[mt][3] = *(const u32*)&sAl[ar + 8][kb + 8];
            }
#pragma unroll
            for (int nt = 0; nt < 4; nt++) {
                int brr = wn * 32 + nt * 8 + g;
                u32 bh[2], bl[2];
                bh[0] = *(const u32*)&sBh[brr][kb];
                bh[1] = *(const u32*)&sBh[brr][kb + 8];
                bl[0] = *(const u32*)&sBl[brr][kb];
                bl[1] = *(const u32*)&sBl[brr][kb + 8];
#pragma unroll
                for (int mt = 0; mt < 2; mt++) {
                    mma16816(acc[mt][nt], ah[mt], bh);
                    mma16816(acc[mt][nt], ah[mt], bl);
                    mma16816(acc[mt][nt], al[mt], bh);
                }
            }
        }

        if (more) {
            __syncthreads();   // everyone done reading current tiles
            BG_STORE();
            __syncthreads();   // tiles for k0+32 visible
        }
    }
    #undef BG_FETCH
    #undef BG_STORE

#pragma unroll
    for (int mt = 0; mt < 2; mt++) {
        int m0 = row0 + wm * 32 + mt * 16 + g;
#pragma unroll
        for (int nt = 0; nt < 4; nt++) {
            int n = col0 + wn * 32 + nt * 8 + tg * 2;
            float2 v0 = make_float2(acc[mt][nt][0], acc[mt][nt][1]);
            float2 v1 = make_float2(acc[mt][nt][2], acc[mt][nt][3]);
            if (SIG) {
                v0.x = 1.f / (1.f + __expf(-v0.x));
                v0.y = 1.f / (1.f + __expf(-v0.y));
                v1.x = 1.f / (1.f + __expf(-v1.x));
                v1.y = 1.f / (1.f + __expf(-v1.y));
            }
            *(float2*)&C[(size_t)m0 * N + n] = v0;
            *(float2*)&C[(size_t)(m0 + 8) * N + n] = v1;
        }
    }
}

// ---------------------------------------------------------------------------
// Convert Q/K rows (from the fused qkv buffer) to split-bf16 [b,head,s,16];
// for Q also apply 2x-1 and emit c = 16 - sum(pq).
// ---------------------------------------------------------------------------
template <bool ISQ>
__global__ void convqk_kernel(const float* __restrict__ src, int srcStride, int colOff,
                              u16* __restrict__ dh, u16* __restrict__ dl,
                              float* __restrict__ qc, int nheads)
{
    int tid = blockIdx.x * blockDim.x + threadIdx.x;
    int total = MROWS * nheads;
    if (tid >= total) return;
    int h = tid % nheads;
    int ms = tid / nheads;
    int b = ms / SS, s = ms - b * SS;

    const float4* p = (const float4*)(src + (size_t)ms * srcStride + colOff + h * QKB);
    float c = (float)QKB;
    __align__(16) u32 oh[8];
    __align__(16) u32 ol[8];
#pragma unroll
    for (int i = 0; i < 4; i++) {
        float4 v = p[i];
        float xs[4] = {v.x, v.y, v.z, v.w};
        float hs[4], ls[4];
#pragma unroll
        for (int j = 0; j < 4; j++) {
            float x = xs[j];
            if (ISQ) { c -= x; x = 2.f * x - 1.f; }
            bsplit(x, hs[j], ls[j]);
        }
        oh[i * 2]     = packbf2(hs[0], hs[1]);
        oh[i * 2 + 1] = packbf2(hs[2], hs[3]);
        ol[i * 2]     = packbf2(ls[0], ls[1]);
        ol[i * 2 + 1] = packbf2(ls[2], ls[3]);
    }
    size_t orow = ((size_t)(b * nheads + h) * SS + s) * QKB;
    ((float4*)(dh + orow))[0] = *(float4*)&oh[0];
    ((float4*)(dh + orow))[1] = *(float4*)&oh[4];
    ((float4*)(dl + orow))[0] = *(float4*)&ol[0];
    ((float4*)(dl + orow))[1] = *(float4*)&ol[4];
    if (ISQ) qc[(size_t)(b * nheads + h) * SS + s] = c;
}

// ---------------------------------------------------------------------------
// Transpose + split V (from qkv buffer) -> [b,kv,vd,S] bf16 hi/lo.
// ---------------------------------------------------------------------------
#define VOFF (NH * QKB + NKV * QKB)   // 320

__global__ void __launch_bounds__(256) convv_kernel(
    const float* __restrict__ qkv, u16* __restrict__ vth, u16* __restrict__ vtl)
{
    __shared__ __align__(16) float tile[64][33];
    const int s0 = blockIdx.x * 64;
    const int kv = blockIdx.y;
    const int b  = blockIdx.z;
    const int t  = threadIdx.x;

    {
        int sl = t >> 2, vg = (t & 3) * 8;
        const float4* src = (const float4*)(qkv + ((size_t)(b * SS + s0 + sl)) * NQKV
                                            + VOFF + kv * VB + vg);
        float4 v0 = src[0], v1 = src[1];
        tile[sl][vg + 0] = v0.x; tile[sl][vg + 1] = v0.y;
        tile[sl][vg + 2] = v0.z; tile[sl][vg + 3] = v0.w;
        tile[sl][vg + 4] = v1.x; tile[sl][vg + 5] = v1.y;
        tile[sl][vg + 6] = v1.z; tile[sl][vg + 7] = v1.w;
    }
    __syncthreads();
    {
        int vd = t >> 3, sc = (t & 7) * 8;
        __align__(16) u32 oh[4];
        __align__(16) u32 ol[4];
#pragma unroll
        for (int j = 0; j < 4; j++) {
            float x0 = tile[sc + 2 * j][vd], x1 = tile[sc + 2 * j + 1][vd];
            float h0, l0, h1, l1;
            bsplit(x0, h0, l0); bsplit(x1, h1, l1);
            oh[j] = packbf2(h0, h1);
            ol[j] = packbf2(l0, l1);
        }
        size_t orow = (((size_t)(b * NKV + kv) * VB + vd) * SS) + s0 + sc;
        *(float4*)(vth + orow) = *(float4*)&oh[0];
        *(float4*)(vtl + orow) = *(float4*)&ol[0];
    }
}

// ---------------------------------------------------------------------------
// Flash-style causal attention on tensor cores (mma.sync bf16, hi/lo split).
// LPT scheduling: heaviest query blocks (largest qblk) launch FIRST.
// ---------------------------------------------------------------------------
#define QM 128
#define BN 128
#define SKP 24
#define SVP (BN + 8)

__global__ void __launch_bounds__(256) rosa_attn_mma(
    const u16* __restrict__ qmh, const u16* __restrict__ qml,
    const float* __restrict__ qc,
    const u16* __restrict__ kh, const u16* __restrict__ kl,
    const u16* __restrict__ vth, const u16* __restrict__ vtl,
    const float* __restrict__ e0, const float* __restrict__ e1,
    u16* __restrict__ ovhh, u16* __restrict__ ovhl)
{
    __shared__ __align__(16) u16 skh[BN][SKP];
    __shared__ __align__(16) u16 skl[BN][SKP];
    __shared__ __align__(16) u16 svh[VB][SVP];
    __shared__ __align__(16) u16 svl[VB][SVP];

    const int qblk = gridDim.x - 1 - blockIdx.x;   // LPT: heavy blocks first
    const int h = blockIdx.y, b = blockIdx.z;
    const int kv = h / NREP;
    const int tid = threadIdx.x, warp = tid >> 5, lane = tid & 31;
    const int g = lane >> 2, tg = lane & 3;
    const int qw0 = qblk * QM + warp * 16;

    const u16* qbh = qmh + ((size_t)(b * NH + h) * SS) * QKB;
    const u16* qbl = qml + ((size_t)(b * NH + h) * SS) * QKB;
    size_t a0 = (size_t)(qw0 + g) * QKB + tg * 2;
    u32 a_hi[4], a_lo[4];
    a_hi[0] = *(const u32*)(qbh + a0);
    a_hi[1] = *(const u32*)(qbh + a0 + 8 * QKB);
    a_hi[2] = *(const u32*)(qbh + a0 + 8);
    a_hi[3] = *(const u32*)(qbh + a0 + 8 * QKB + 8);
    a_lo[0] = *(const u32*)(qbl + a0);
    a_lo[1] = *(const u32*)(qbl + a0 + 8 * QKB);
    a_lo[2] = *(const u32*)(qbl + a0 + 8);
    a_lo[3] = *(const u32*)(qbl + a0 + 8 * QKB + 8);
    const float* qcb = qc + (size_t)(b * NH + h) * SS + qw0;
    const float c0 = qcb[g], c1 = qcb[g + 8];
    const int qg0 = qw0 + g, qg1 = qg0 + 8;

    float num[4][4];
#pragma unroll
    for (int i = 0; i < 4; i++)
#pragma unroll
        for (int j = 0; j < 4; j++) num[i][j] = 0.f;
    float den0 = 0.f, den1 = 0.f;

    const u16* kbh = kh + ((size_t)(b * NKV + kv) * SS) * QKB;
    const u16* kbl = kl + ((size_t)(b * NKV + kv) * SS) * QKB;
    const u16* vbh = vth + ((size_t)(b * NKV + kv) * VB) * SS;
    const u16* vbl = vtl + ((size_t)(b * NKV + kv) * VB) * SS;

    for (int t0 = 0; t0 <= qblk; t0++) {
        {
            int r = tid & 127;
            const u16* src = ((tid < 128) ? kbh : kbl) + ((size_t)(t0 * BN + r)) * QKB;
            u16 (*dst)[SKP] = (tid < 128) ? skh : skl;
            float4 v0 = ((const float4*)src)[0];
            float4 v1 = ((const float4*)src)[1];
            *(float4*)&dst[r][0] = v0;
            *(float4*)&dst[r][8] = v1;
        }
#pragma unroll
        for (int i = 0; i < 2; i++) {
            int idx = tid + i * 256;
            int row = idx >> 4, c4 = idx & 15;
            *(float4*)&svh[row][c4 * 8] =
                *((const float4*)(vbh + (size_t)row * SS + t0 * BN) + c4);
            *(float4*)&svl[row][c4 * 8] =
                *((const float4*)(vbl + (size_t)row * SS + t0 * BN) + c4);
        }
        __syncthreads();

        const bool diag = (t0 == qblk);
        for (int kc = 0; kc < 8; kc++) {
            float sc[2][4];
#pragma unroll
            for (int hf = 0; hf < 2; hf++) {
                int n8 = kc * 16 + hf * 8;
                u32 bh_[2], bl_[2];
                const u16* kr  = &skh[n8 + g][tg * 2];
                const u16* krl = &skl[n8 + g][tg * 2];
                bh_[0] = *(const u32*)kr;        bh_[1] = *(const u32*)(kr + 8);
                bl_[0] = *(const u32*)krl;       bl_[1] = *(const u32*)(krl + 8);
                float cc[4] = {0.f, 0.f, 0.f, 0.f};
                mma16816(cc, a_hi, bh_);
                mma16816(cc, a_hi, bl_);
                mma16816(cc, a_lo, bh_);
                sc[hf][0] = cc[0]; sc[hf][1] = cc[1];
                sc[hf][2] = cc[2]; sc[hf][3] = cc[3];
            }
            u32 Ah[4], Al[4];
#pragma unroll
            for (int hf = 0; hf < 2; hf++) {
                int kb = t0 * BN + kc * 16 + hf * 8 + tg * 2;
                float p0 = __expf(sc[hf][0] + c0);
                float p1 = __expf(sc[hf][1] + c0);
                float p2 = __expf(sc[hf][2] + c1);
                float p3 = __expf(sc[hf][3] + c1);
                if (diag) {
                    if (kb     > qg0) p0 = 0.f;
                    if (kb + 1 > qg0) p1 = 0.f;
                    if (kb     > qg1) p2 = 0.f;
                    if (kb + 1 > qg1) p3 = 0.f;
                }
                den0 += p0 + p1;
                den1 += p2 + p3;
                float h0, l0, h1, l1, h2, l2, h3, l3;
                bsplit(p0, h0, l0); bsplit(p1, h1, l1);
                bsplit(p2, h2, l2); bsplit(p3, h3, l3);
                Ah[hf * 2]     = packbf2(h0, h1);
                Ah[hf * 2 + 1] = packbf2(h2, h3);
                Al[hf * 2]     = packbf2(l0, l1);
                Al[hf * 2 + 1] = packbf2(l2, l3);
            }
#pragma unroll
            for (int vt = 0; vt < 4; vt++) {
                u32 bvh[2], bvl[2];
                const u16* vr  = &svh[vt * 8 + g][kc * 16 + tg * 2];
                const u16* vrl = &svl[vt * 8 + g][kc * 16 + tg * 2];
                bvh[0] = *(const u32*)vr;   bvh[1] = *(const u32*)(vr + 8);
                bvl[0] = *(const u32*)vrl;  bvl[1] = *(const u32*)(vrl + 8);
                mma16816(num[vt], Ah, bvh);
                mma16816(num[vt], Ah, bvl);
                mma16816(num[vt], Al, bvh);
            }
        }
        __syncthreads();
    }

    den0 += __shfl_xor_sync(0xffffffffu, den0, 1);
    den0 += __shfl_xor_sync(0xffffffffu, den0, 2);
    den1 += __shfl_xor_sync(0xffffffffu, den1, 1);
    den1 += __shfl_xor_sync(0xffffffffu, den1, 2);
    const float inv0 = 1.f / den0, inv1 = 1.f / den1;

#pragma unroll
    for (int vt = 0; vt < 4; vt++) {
        int vd = vt * 8 + tg * 2;
        float a00 = e0[h * VB + vd],     b00 = e1[h * VB + vd];
        float a01 = e0[h * VB + vd + 1], b01 = e1[h * VB + vd + 1];
        float o00 = fmaf(b00 - a00, num[vt][0] * inv0, a00);
        float o01 = fmaf(b01 - a01, num[vt][1] * inv0, a01);
        float o10 = fmaf(b00 - a00, num[vt][2] * inv1, a00);
        float o11 = fmaf(b01 - a01, num[vt][3] * inv1, a01);
        float h0, l0, h1, l1;
        size_t i0 = ((size_t)(b * SS + qg0) * NH + h) * VB + vd;
        size_t i1 = ((size_t)(b * SS + qg1) * NH + h) * VB + vd;
        bsplit(o00, h0, l0); bsplit(o01, h1, l1);
        *(u32*)&ovhh[i0] = packbf2(h0, h1);
        *(u32*)&ovhl[i0] = packbf2(l0, l1);
        bsplit(o10, h0, l0); bsplit(o11, h1, l1);
        *(u32*)&ovhh[i1] = packbf2(h0, h1);
        *(u32*)&ovhl[i1] = packbf2(l0, l1);
    }
}

// ---------------------------------------------------------------------------
extern "C" void kernel_launch(void* const* d_in, const int* in_sizes, int n_in,
                              void* d_out, int out_size)
{
    const float* hs = (const float*)d_in[0];
    const float* Wq = (const float*)d_in[1];
    const float* Wk = (const float*)d_in[2];
    const float* Wv = (const float*)d_in[3];
    const float* Wo = (const float*)d_in[4];
    const float* e0 = (const float*)d_in[5];
    const float* e1 = (const float*)d_in[6];
    float* out = (float*)d_out;

    u16 *hsh, *hsl, *wth, *wtl, *woth, *wotl, *ovhh, *ovhl;
    u16 *qmh, *qml, *kh_, *kl_, *vth, *vtl;
    float *qkv, *qcp;
    cudaGetSymbolAddress((void**)&hsh,  g_hsh);
    cudaGetSymbolAddress((void**)&hsl,  g_hsl);
    cudaGetSymbolAddress((void**)&wth,  g_wth);
    cudaGetSymbolAddress((void**)&wtl,  g_wtl);
    cudaGetSymbolAddress((void**)&woth, g_woth);
    cudaGetSymbolAddress((void**)&wotl, g_wotl);
    cudaGetSymbolAddress((void**)&qkv,  g_qkv);
    cudaGetSymbolAddress((void**)&ovhh, g_ovhh);
    cudaGetSymbolAddress((void**)&ovhl, g_ovhl);
    cudaGetSymbolAddress((void**)&qcp,  g_qc);
    cudaGetSymbolAddress((void**)&qmh,  g_qmh);
    cudaGetSymbolAddress((void**)&qml,  g_qml);
    cudaGetSymbolAddress((void**)&kh_,  g_kh);
    cudaGetSymbolAddress((void**)&kl_,  g_kl);
    cudaGetSymbolAddress((void**)&vth,  g_vth);
    cudaGetSymbolAddress((void**)&vtl,  g_vtl);

    convert_split_kernel<<<(MROWS * DD / 8 + 255) / 256, 256>>>(hs, hsh, hsl, MROWS * DD);
    transpose_split_kernel<<<dim3(256 / 32, DD / 32), 256>>>(Wq, DD, 256, wth, wtl, DD, 0);
    transpose_split_kernel<<<dim3(64 / 32,  DD / 32), 256>>>(Wk, DD, 64,  wth, wtl, DD, 256);
    transpose_split_kernel<<<dim3(128 / 32, DD / 32), 256>>>(Wv, DD, 128, wth, wtl, DD, 320);
    transpose_split_kernel<<<dim3(DD / 32,  KO / 32), 256>>>(Wo, KO, DD,  woth, wotl, KO, 0);

    bgemm_kernel<1><<<dim3(NQKV / 64, MROWS / 128), 256>>>(
        hsh, hsl, wth, wtl, qkv, MROWS, NQKV, DD);

    convqk_kernel<true ><<<(MROWS * NH  + 127) / 128, 128>>>(qkv, NQKV, 0,   qmh, qml, qcp, NH);
    convqk_kernel<false><<<(MROWS * NKV + 127) / 128, 128>>>(qkv, NQKV, 256, kh_, kl_, nullptr, NKV);
    convv_kernel<<<dim3(SS / 64, NKV, BB), 256>>>(qkv, vth, vtl);

    rosa_attn_mma<<<dim3(SS / QM, NH, BB), 256>>>(qmh, qml, qcp, kh_, kl_, vth, vtl,
                                                  e0, e1, ovhh, ovhl);

    bgemm_kernel<0><<<dim3(DD / 64, MROWS / 128), 256>>>(
        ovhh, ovhl, woth, wotl, out, MROWS, DD, KO);
}

// round 11
// speedup vs baseline: 1.5881x; 1.5881x over previous
#include <cuda_runtime.h>
#include <cuda_bf16.h>
#include <math.h>

#define BB 2
#define SS 2048
#define DD 1024
#define NH 16
#define NKV 4
#define QKB 16
#define VB 32
#define NREP (NH / NKV)
#define MROWS (BB * SS)       // 4096
#define NQKV (NH * QKB + NKV * QKB + NKV * VB)   // 448
#define KO (NH * VB)          // 512

typedef unsigned int u32;
typedef unsigned short u16;

// ---- bf16 split helpers ----
__device__ __forceinline__ void bsplit(float x, float& hi, float& lo) {
    float h = __bfloat162float(__float2bfloat16(x));
    hi = h; lo = x - h;
}
__device__ __forceinline__ u32 packbf2(float a, float b) {   // a -> low half
    __nv_bfloat162 t = __floats2bfloat162_rn(a, b);
    return *(u32*)&t;
}

// ---- mma.sync m16n8k16 bf16, f32 accum (fragment mappings verified R6) ----
__device__ __forceinline__ void mma16816(float c[4], const u32 a[4], const u32 b[2]) {
    asm volatile(
        "mma.sync.aligned.m16n8k16.row.col.f32.bf16.bf16.f32 "
        "{%0,%1,%2,%3}, {%4,%5,%6,%7}, {%8,%9}, {%0,%1,%2,%3};"
        : "+f"(c[0]), "+f"(c[1]), "+f"(c[2]), "+f"(c[3])
        : "r"(a[0]), "r"(a[1]), "r"(a[2]), "r"(a[3]), "r"(b[0]), "r"(b[1]));
}

// ---- scratch (__device__ globals; no allocation allowed) ----
__device__ __align__(16) u16 g_hsh[MROWS * DD];
__device__ __align__(16) u16 g_hsl[MROWS * DD];
__device__ __align__(16) u16 g_wth[NQKV * DD];
__device__ __align__(16) u16 g_wtl[NQKV * DD];
__device__ __align__(16) u16 g_woth[DD * KO];
__device__ __align__(16) u16 g_wotl[DD * KO];
__device__ __align__(16) float g_qkv[MROWS * NQKV];
__device__ __align__(16) u16 g_ovhh[MROWS * KO];
__device__ __align__(16) u16 g_ovhl[MROWS * KO];
__device__ __align__(16) u16 g_qmh[BB * NH * SS * QKB];
__device__ __align__(16) u16 g_qml[BB * NH * SS * QKB];
__device__ __align__(16) float g_qc[BB * NH * SS];
__device__ __align__(16) u16 g_kh[BB * NKV * SS * QKB];
__device__ __align__(16) u16 g_kl[BB * NKV * SS * QKB];
__device__ __align__(16) u16 g_vth[BB * NKV * VB * SS];
__device__ __align__(16) u16 g_vtl[BB * NKV * VB * SS];

// ---------------------------------------------------------------------------
// Elementwise fp32 -> split bf16 (hi/lo). 8 elems/thread, all float4.
// ---------------------------------------------------------------------------
__global__ void convert_split_kernel(const float* __restrict__ src,
                                     u16* __restrict__ dh, u16* __restrict__ dl,
                                     int total)
{
    int idx = blockIdx.x * blockDim.x + threadIdx.x;
    int base = idx * 8;
    if (base >= total) return;
    float4 v0 = *(const float4*)(src + base);
    float4 v1 = *(const float4*)(src + base + 4);
    float xs[8] = {v0.x, v0.y, v0.z, v0.w, v1.x, v1.y, v1.z, v1.w};
    __align__(16) u32 oh[4];
    __align__(16) u32 ol[4];
#pragma unroll
    for (int i = 0; i < 4; i++) {
        float h0, l0, h1, l1;
        bsplit(xs[2 * i], h0, l0);
        bsplit(xs[2 * i + 1], h1, l1);
        oh[i] = packbf2(h0, h1);
        ol[i] = packbf2(l0, l1);
    }
    *(float4*)(dh + base) = *(float4*)&oh[0];
    *(float4*)(dl + base) = *(float4*)&ol[0];
}

// ---------------------------------------------------------------------------
// Transpose + split a weight: src fp32 [K][N] -> dst bf16 [nOff+n][K].
// ---------------------------------------------------------------------------
__global__ void __launch_bounds__(256) transpose_split_kernel(
    const float* __restrict__ src, int K, int N,
    u16* __restrict__ dh, u16* __restrict__ dl, int dstStride, int nOff)
{
    __shared__ __align__(16) float tile[32][33];
    const int n0 = blockIdx.x * 32;
    const int k0 = blockIdx.y * 32;
    const int t = threadIdx.x;
    {
        int r = t >> 3, c = (t & 7) * 4;
        float4 v = *(const float4*)(src + (size_t)(k0 + r) * N + n0 + c);
        tile[r][c + 0] = v.x; tile[r][c + 1] = v.y;
        tile[r][c + 2] = v.z; tile[r][c + 3] = v.w;
    }
    __syncthreads();
    {
        int col = t >> 3, k4 = (t & 7) * 4;
        __align__(8) u32 oh[2];
        __align__(8) u32 ol[2];
#pragma unroll
        for (int i = 0; i < 2; i++) {
            float h0, l0, h1, l1;
            bsplit(tile[k4 + 2 * i][col], h0, l0);
            bsplit(tile[k4 + 2 * i + 1][col], h1, l1);
            oh[i] = packbf2(h0, h1);
            ol[i] = packbf2(l0, l1);
        }
        size_t o = (size_t)(nOff + n0 + col) * dstStride + k0 + k4;
        *(float2*)(dh + o) = *(float2*)&oh[0];
        *(float2*)(dl + o) = *(float2*)&ol[0];
    }
}

// ---------------------------------------------------------------------------
// Split-bf16 tensor-core GEMM: C[M,N] = A[M,K] @ B^T (B stored [N][K]).
// Tile 128x64x32, 256 threads, warp tile 32x32, 3 MMAs per product.
// (Exact R8 version — verified at 280.6 us total.)
// ---------------------------------------------------------------------------
template <int SIG>
__global__ void __launch_bounds__(256) bgemm_kernel(
    const u16* __restrict__ Ah, const u16* __restrict__ Al,
    const u16* __restrict__ Bh, const u16* __restrict__ Bl,
    float* __restrict__ C, int M, int N, int K)
{
    __shared__ __align__(16) u16 sAh[128][40];
    __shared__ __align__(16) u16 sAl[128][40];
    __shared__ __align__(16) u16 sBh[64][40];
    __shared__ __align__(16) u16 sBl[64][40];

    const int tid = threadIdx.x, warp = tid >> 5, lane = tid & 31;
    const int g = lane >> 2, tg = lane & 3;
    const int wm = warp >> 1, wn = warp & 1;
    const int row0 = blockIdx.y * 128, col0 = blockIdx.x * 64;

    float acc[2][4][4];
#pragma unroll
    for (int mt = 0; mt < 2; mt++)
#pragma unroll
        for (int nt = 0; nt < 4; nt++)
#pragma unroll
            for (int i = 0; i < 4; i++) acc[mt][nt][i] = 0.f;

    for (int k0 = 0; k0 < K; k0 += 32) {
#pragma unroll
        for (int i = 0; i < 2; i++) {      // A tile: 128 rows x 32 halves
            int ch = tid + i * 256;
            int r = ch >> 2, c = (ch & 3) * 8;
            *(float4*)&sAh[r][c] = *(const float4*)(Ah + (size_t)(row0 + r) * K + k0 + c);
            *(float4*)&sAl[r][c] = *(const float4*)(Al + (size_t)(row0 + r) * K + k0 + c);
        }
        {                                   // B tile: 64 rows x 32 halves
            int r = tid >> 2, c = (tid & 3) * 8;
            *(float4*)&sBh[r][c] = *(const float4*)(Bh + (size_t)(col0 + r) * K + k0 + c);
            *(float4*)&sBl[r][c] = *(const float4*)(Bl + (size_t)(col0 + r) * K + k0 + c);
        }
        __syncthreads();

#pragma unroll
        for (int k16 = 0; k16 < 2; k16++) {
            const int kb = k16 * 16 + tg * 2;
            u32 ah[2][4], al[2][4];
#pragma unroll
            for (int mt = 0; mt < 2; mt++) {
                int ar = wm * 32 + mt * 16 + g;
                ah[mt][0] = *(const u32*)&sAh[ar][kb];
                ah[mt][1] = *(const u32*)&sAh[ar + 8][kb];
                ah[mt][2] = *(const u32*)&sAh[ar][kb + 8];
                ah[mt][3] = *(const u32*)&sAh[ar + 8][kb + 8];
                al[mt][0] = *(const u32*)&sAl[ar][kb];
                al[mt][1] = *(const u32*)&sAl[ar + 8][kb];
                al[mt][2] = *(const u32*)&sAl[ar][kb + 8];
                al[mt][3] = *(const u32*)&sAl[ar + 8][kb + 8];
            }
#pragma unroll
            for (int nt = 0; nt < 4; nt++) {
                int br = wn * 32 + nt * 8 + g;
                u32 bh[2], bl[2];
                bh[0] = *(const u32*)&sBh[br][kb];
                bh[1] = *(const u32*)&sBh[br][kb + 8];
                bl[0] = *(const u32*)&sBl[br][kb];
                bl[1] = *(const u32*)&sBl[br][kb + 8];
#pragma unroll
                for (int mt = 0; mt < 2; mt++) {
                    mma16816(acc[mt][nt], ah[mt], bh);
                    mma16816(acc[mt][nt], ah[mt], bl);
                    mma16816(acc[mt][nt], al[mt], bh);
                }
            }
        }
        __syncthreads();
    }

#pragma unroll
    for (int mt = 0; mt < 2; mt++) {
        int m0 = row0 + wm * 32 + mt * 16 + g;
#pragma unroll
        for (int nt = 0; nt < 4; nt++) {
            int n = col0 + wn * 32 + nt * 8 + tg * 2;
            float2 v0 = make_float2(acc[mt][nt][0], acc[mt][nt][1]);
            float2 v1 = make_float2(acc[mt][nt][2], acc[mt][nt][3]);
            if (SIG) {
                v0.x = 1.f / (1.f + __expf(-v0.x));
                v0.y = 1.f / (1.f + __expf(-v0.y));
                v1.x = 1.f / (1.f + __expf(-v1.x));
                v1.y = 1.f / (1.f + __expf(-v1.y));
            }
            *(float2*)&C[(size_t)m0 * N + n] = v0;
            *(float2*)&C[(size_t)(m0 + 8) * N + n] = v1;
        }
    }
}

// ---------------------------------------------------------------------------
// Convert Q/K rows (from the fused qkv buffer) to split-bf16 [b,head,s,16];
// for Q also apply 2x-1 and emit c = 16 - sum(pq).
// ---------------------------------------------------------------------------
template <bool ISQ>
__global__ void convqk_kernel(const float* __restrict__ src, int srcStride, int colOff,
                              u16* __restrict__ dh, u16* __restrict__ dl,
                              float* __restrict__ qc, int nheads)
{
    int tid = blockIdx.x * blockDim.x + threadIdx.x;
    int total = MROWS * nheads;
    if (tid >= total) return;
    int h = tid % nheads;
    int ms = tid / nheads;
    int b = ms / SS, s = ms - b * SS;

    const float4* p = (const float4*)(src + (size_t)ms * srcStride + colOff + h * QKB);
    float c = (float)QKB;
    __align__(16) u32 oh[8];
    __align__(16) u32 ol[8];
#pragma unroll
    for (int i = 0; i < 4; i++) {
        float4 v = p[i];
        float xs[4] = {v.x, v.y, v.z, v.w};
        float hs[4], ls[4];
#pragma unroll
        for (int j = 0; j < 4; j++) {
            float x = xs[j];
            if (ISQ) { c -= x; x = 2.f * x - 1.f; }
            bsplit(x, hs[j], ls[j]);
        }
        oh[i * 2]     = packbf2(hs[0], hs[1]);
        oh[i * 2 + 1] = packbf2(hs[2], hs[3]);
        ol[i * 2]     = packbf2(ls[0], ls[1]);
        ol[i * 2 + 1] = packbf2(ls[2], ls[3]);
    }
    size_t orow = ((size_t)(b * nheads + h) * SS + s) * QKB;
    ((float4*)(dh + orow))[0] = *(float4*)&oh[0];
    ((float4*)(dh + orow))[1] = *(float4*)&oh[4];
    ((float4*)(dl + orow))[0] = *(float4*)&ol[0];
    ((float4*)(dl + orow))[1] = *(float4*)&ol[4];
    if (ISQ) qc[(size_t)(b * nheads + h) * SS + s] = c;
}

// ---------------------------------------------------------------------------
// Transpose + split V (from qkv buffer) -> [b,kv,vd,S] bf16 hi/lo.
// ---------------------------------------------------------------------------
#define VOFF (NH * QKB + NKV * QKB)   // 320

__global__ void __launch_bounds__(256) convv_kernel(
    const float* __restrict__ qkv, u16* __restrict__ vth, u16* __restrict__ vtl)
{
    __shared__ __align__(16) float tile[64][33];
    const int s0 = blockIdx.x * 64;
    const int kv = blockIdx.y;
    const int b  = blockIdx.z;
    const int t  = threadIdx.x;

    {
        int sl = t >> 2, vg = (t & 3) * 8;
        const float4* src = (const float4*)(qkv + ((size_t)(b * SS + s0 + sl)) * NQKV
                                            + VOFF + kv * VB + vg);
        float4 v0 = src[0], v1 = src[1];
        tile[sl][vg + 0] = v0.x; tile[sl][vg + 1] = v0.y;
        tile[sl][vg + 2] = v0.z; tile[sl][vg + 3] = v0.w;
        tile[sl][vg + 4] = v1.x; tile[sl][vg + 5] = v1.y;
        tile[sl][vg + 6] = v1.z; tile[sl][vg + 7] = v1.w;
    }
    __syncthreads();
    {
        int vd = t >> 3, sc = (t & 7) * 8;
        __align__(16) u32 oh[4];
        __align__(16) u32 ol[4];
#pragma unroll
        for (int j = 0; j < 4; j++) {
            float x0 = tile[sc + 2 * j][vd], x1 = tile[sc + 2 * j + 1][vd];
            float h0, l0, h1, l1;
            bsplit(x0, h0, l0); bsplit(x1, h1, l1);
            oh[j] = packbf2(h0, h1);
            ol[j] = packbf2(l0, l1);
        }
        size_t orow = (((size_t)(b * NKV + kv) * VB + vd) * SS) + s0 + sc;
        *(float4*)(vth + orow) = *(float4*)&oh[0];
        *(float4*)(vtl + orow) = *(float4*)&ol[0];
    }
}

// ---------------------------------------------------------------------------
// Flash-style causal attention on tensor cores (mma.sync bf16, hi/lo split).
// LPT scheduling: heaviest query blocks (largest qblk) launch FIRST.
// ---------------------------------------------------------------------------
#define QM 128
#define BN 128
#define SKP 24
#define SVP (BN + 8)

__global__ void __launch_bounds__(256) rosa_attn_mma(
    const u16* __restrict__ qmh, const u16* __restrict__ qml,
    const float* __restrict__ qc,
    const u16* __restrict__ kh, const u16* __restrict__ kl,
    const u16* __restrict__ vth, const u16* __restrict__ vtl,
    const float* __restrict__ e0, const float* __restrict__ e1,
    u16* __restrict__ ovhh, u16* __restrict__ ovhl)
{
    __shared__ __align__(16) u16 skh[BN][SKP];
    __shared__ __align__(16) u16 skl[BN][SKP];
    __shared__ __align__(16) u16 svh[VB][SVP];
    __shared__ __align__(16) u16 svl[VB][SVP];

    const int qblk = gridDim.x - 1 - blockIdx.x;   // LPT: heavy blocks first
    const int h = blockIdx.y, b = blockIdx.z;
    const int kv = h / NREP;
    const int tid = threadIdx.x, warp = tid >> 5, lane = tid & 31;
    const int g = lane >> 2, tg = lane & 3;
    const int qw0 = qblk * QM + warp * 16;

    const u16* qbh = qmh + ((size_t)(b * NH + h) * SS) * QKB;
    const u16* qbl = qml + ((size_t)(b * NH + h) * SS) * QKB;
    size_t a0 = (size_t)(qw0 + g) * QKB + tg * 2;
    u32 a_hi[4], a_lo[4];
    a_hi[0] = *(const u32*)(qbh + a0);
    a_hi[1] = *(const u32*)(qbh + a0 + 8 * QKB);
    a_hi[2] = *(const u32*)(qbh + a0 + 8);
    a_hi[3] = *(const u32*)(qbh + a0 + 8 * QKB + 8);
    a_lo[0] = *(const u32*)(qbl + a0);
    a_lo[1] = *(const u32*)(qbl + a0 + 8 * QKB);
    a_lo[2] = *(const u32*)(qbl + a0 + 8);
    a_lo[3] = *(const u32*)(qbl + a0 + 8 * QKB + 8);
    const float* qcb = qc + (size_t)(b * NH + h) * SS + qw0;
    const float c0 = qcb[g], c1 = qcb[g + 8];
    const int qg0 = qw0 + g, qg1 = qg0 + 8;

    float num[4][4];
#pragma unroll
    for (int i = 0; i < 4; i++)
#pragma unroll
        for (int j = 0; j < 4; j++) num[i][j] = 0.f;
    float den0 = 0.f, den1 = 0.f;

    const u16* kbh = kh + ((size_t)(b * NKV + kv) * SS) * QKB;
    const u16* kbl = kl + ((size_t)(b * NKV + kv) * SS) * QKB;
    const u16* vbh = vth + ((size_t)(b * NKV + kv) * VB) * SS;
    const u16* vbl = vtl + ((size_t)(b * NKV + kv) * VB) * SS;

    for (int t0 = 0; t0 <= qblk; t0++) {
        {
            int r = tid & 127;
            const u16* src = ((tid < 128) ? kbh : kbl) + ((size_t)(t0 * BN + r)) * QKB;
            u16 (*dst)[SKP] = (tid < 128) ? skh : skl;
            float4 v0 = ((const float4*)src)[0];
            float4 v1 = ((const float4*)src)[1];
            *(float4*)&dst[r][0] = v0;
            *(float4*)&dst[r][8] = v1;
        }
#pragma unroll
        for (int i = 0; i < 2; i++) {
            int idx = tid + i * 256;
            int row = idx >> 4, c4 = idx & 15;
            *(float4*)&svh[row][c4 * 8] =
                *((const float4*)(vbh + (size_t)row * SS + t0 * BN) + c4);
            *(float4*)&svl[row][c4 * 8] =
                *((const float4*)(vbl + (size_t)row * SS + t0 * BN) + c4);
        }
        __syncthreads();

        const bool diag = (t0 == qblk);
        for (int kc = 0; kc < 8; kc++) {
            float sc[2][4];
#pragma unroll
            for (int hf = 0; hf < 2; hf++) {
                int n8 = kc * 16 + hf * 8;
                u32 bh_[2], bl_[2];
                const u16* kr  = &skh[n8 + g][tg * 2];
                const u16* krl = &skl[n8 + g][tg * 2];
                bh_[0] = *(const u32*)kr;        bh_[1] = *(const u32*)(kr + 8);
                bl_[0] = *(const u32*)krl;       bl_[1] = *(const u32*)(krl + 8);
                float cc[4] = {0.f, 0.f, 0.f, 0.f};
                mma16816(cc, a_hi, bh_);
                mma16816(cc, a_hi, bl_);
                mma16816(cc, a_lo, bh_);
                sc[hf][0] = cc[0]; sc[hf][1] = cc[1];
                sc[hf][2] = cc[2]; sc[hf][3] = cc[3];
            }
            u32 Ah[4], Al[4];
#pragma unroll
            for (int hf = 0; hf < 2; hf++) {
                int kb = t0 * BN + kc * 16 + hf * 8 + tg * 2;
                float p0 = __expf(sc[hf][0] + c0);
                float p1 = __expf(sc[hf][1] + c0);
                float p2 = __expf(sc[hf][2] + c1);
                float p3 = __expf(sc[hf][3] + c1);
                if (diag) {
                    if (kb     > qg0) p0 = 0.f;
                    if (kb + 1 > qg0) p1 = 0.f;
                    if (kb     > qg1) p2 = 0.f;
                    if (kb + 1 > qg1) p3 = 0.f;
                }
                den0 += p0 + p1;
                den1 += p2 + p3;
                float h0, l0, h1, l1, h2, l2, h3, l3;
                bsplit(p0, h0, l0); bsplit(p1, h1, l1);
                bsplit(p2, h2, l2); bsplit(p3, h3, l3);
                Ah[hf * 2]     = packbf2(h0, h1);
                Ah[hf * 2 + 1] = packbf2(h2, h3);
                Al[hf * 2]     = packbf2(l0, l1);
                Al[hf * 2 + 1] = packbf2(l2, l3);
            }
#pragma unroll
            for (int vt = 0; vt < 4; vt++) {
                u32 bvh[2], bvl[2];
                const u16* vr  = &svh[vt * 8 + g][kc * 16 + tg * 2];
                const u16* vrl = &svl[vt * 8 + g][kc * 16 + tg * 2];
                bvh[0] = *(const u32*)vr;   bvh[1] = *(const u32*)(vr + 8);
                bvl[0] = *(const u32*)vrl;  bvl[1] = *(const u32*)(vrl + 8);
                mma16816(num[vt], Ah, bvh);
                mma16816(num[vt], Ah, bvl);
                mma16816(num[vt], Al, bvh);
            }
        }
        __syncthreads();
    }

    den0 += __shfl_xor_sync(0xffffffffu, den0, 1);
    den0 += __shfl_xor_sync(0xffffffffu, den0, 2);
    den1 += __shfl_xor_sync(0xffffffffu, den1, 1);
    den1 += __shfl_xor_sync(0xffffffffu, den1, 2);
    const float inv0 = 1.f / den0, inv1 = 1.f / den1;

#pragma unroll
    for (int vt = 0; vt < 4; vt++) {
        int vd = vt * 8 + tg * 2;
        float a00 = e0[h * VB + vd],     b00 = e1[h * VB + vd];
        float a01 = e0[h * VB + vd + 1], b01 = e1[h * VB + vd + 1];
        float o00 = fmaf(b00 - a00, num[vt][0] * inv0, a00);
        float o01 = fmaf(b01 - a01, num[vt][1] * inv0, a01);
        float o10 = fmaf(b00 - a00, num[vt][2] * inv1, a00);
        float o11 = fmaf(b01 - a01, num[vt][3] * inv1, a01);
        float h0, l0, h1, l1;
        size_t i0 = ((size_t)(b * SS + qg0) * NH + h) * VB + vd;
        size_t i1 = ((size_t)(b * SS + qg1) * NH + h) * VB + vd;
        bsplit(o00, h0, l0); bsplit(o01, h1, l1);
        *(u32*)&ovhh[i0] = packbf2(h0, h1);
        *(u32*)&ovhl[i0] = packbf2(l0, l1);
        bsplit(o10, h0, l0); bsplit(o11, h1, l1);
        *(u32*)&ovhh[i1] = packbf2(h0, h1);
        *(u32*)&ovhl[i1] = packbf2(l0, l1);
    }
}

// ---------------------------------------------------------------------------
extern "C" void kernel_launch(void* const* d_in, const int* in_sizes, int n_in,
                              void* d_out, int out_size)
{
    const float* hs = (const float*)d_in[0];
    const float* Wq = (const float*)d_in[1];
    const float* Wk = (const float*)d_in[2];
    const float* Wv = (const float*)d_in[3];
    const float* Wo = (const float*)d_in[4];
    const float* e0 = (const float*)d_in[5];
    const float* e1 = (const float*)d_in[6];
    float* out = (float*)d_out;

    u16 *hsh, *hsl, *wth, *wtl, *woth, *wotl, *ovhh, *ovhl;
    u16 *qmh, *qml, *kh_, *kl_, *vth, *vtl;
    float *qkv, *qcp;
    cudaGetSymbolAddress((void**)&hsh,  g_hsh);
    cudaGetSymbolAddress((void**)&hsl,  g_hsl);
    cudaGetSymbolAddress((void**)&wth,  g_wth);
    cudaGetSymbolAddress((void**)&wtl,  g_wtl);
    cudaGetSymbolAddress((void**)&woth, g_woth);
    cudaGetSymbolAddress((void**)&wotl, g_wotl);
    cudaGetSymbolAddress((void**)&qkv,  g_qkv);
    cudaGetSymbolAddress((void**)&ovhh, g_ovhh);
    cudaGetSymbolAddress((void**)&ovhl, g_ovhl);
    cudaGetSymbolAddress((void**)&qcp,  g_qc);
    cudaGetSymbolAddress((void**)&qmh,  g_qmh);
    cudaGetSymbolAddress((void**)&qml,  g_qml);
    cudaGetSymbolAddress((void**)&kh_,  g_kh);
    cudaGetSymbolAddress((void**)&kl_,  g_kl);
    cudaGetSymbolAddress((void**)&vth,  g_vth);
    cudaGetSymbolAddress((void**)&vtl,  g_vtl);

    convert_split_kernel<<<(MROWS * DD / 8 + 255) / 256, 256>>>(hs, hsh, hsl, MROWS * DD);
    transpose_split_kernel<<<dim3(256 / 32, DD / 32), 256>>>(Wq, DD, 256, wth, wtl, DD, 0);
    transpose_split_kernel<<<dim3(64 / 32,  DD / 32), 256>>>(Wk, DD, 64,  wth, wtl, DD, 256);
    transpose_split_kernel<<<dim3(128 / 32, DD / 32), 256>>>(Wv, DD, 128, wth, wtl, DD, 320);
    transpose_split_kernel<<<dim3(DD / 32,  KO / 32), 256>>>(Wo, KO, DD,  woth, wotl, KO, 0);

    bgemm_kernel<1><<<dim3(NQKV / 64, MROWS / 128), 256>>>(
        hsh, hsl, wth, wtl, qkv, MROWS, NQKV, DD);

    convqk_kernel<true ><<<(MROWS * NH  + 127) / 128, 128>>>(qkv, NQKV, 0,   qmh, qml, qcp, NH);
    convqk_kernel<false><<<(MROWS * NKV + 127) / 128, 128>>>(qkv, NQKV, 256, kh_, kl_, nullptr, NKV);
    convv_kernel<<<dim3(SS / 64, NKV, BB), 256>>>(qkv, vth, vtl);

    rosa_attn_mma<<<dim3(SS / QM, NH, BB), 256>>>(qmh, qml, qcp, kh_, kl_, vth, vtl,
                                                  e0, e1, ovhh, ovhl);

    bgemm_kernel<0><<<dim3(DD / 64, MROWS / 128), 256>>>(
        ovhh, ovhl, woth, wotl, out, MROWS, DD, KO);
}

// round 12
// speedup vs baseline: 1.6239x; 1.0226x over previous
#include <cuda_runtime.h>
#include <cuda_bf16.h>
#include <math.h>

#define BB 2
#define SS 2048
#define DD 1024
#define NH 16
#define NKV 4
#define QKB 16
#define VB 32
#define NREP (NH / NKV)
#define MROWS (BB * SS)       // 4096
#define NQKV (NH * QKB + NKV * QKB + NKV * VB)   // 448
#define KO (NH * VB)          // 512

typedef unsigned int u32;
typedef unsigned short u16;

// ---- bf16 split helpers ----
__device__ __forceinline__ void bsplit(float x, float& hi, float& lo) {
    float h = __bfloat162float(__float2bfloat16(x));
    hi = h; lo = x - h;
}
__device__ __forceinline__ u32 packbf2(float a, float b) {   // a -> low half
    __nv_bfloat162 t = __floats2bfloat162_rn(a, b);
    return *(u32*)&t;
}

// ---- mma.sync m16n8k16 bf16, f32 accum (fragment mappings verified R6) ----
__device__ __forceinline__ void mma16816(float c[4], const u32 a[4], const u32 b[2]) {
    asm volatile(
        "mma.sync.aligned.m16n8k16.row.col.f32.bf16.bf16.f32 "
        "{%0,%1,%2,%3}, {%4,%5,%6,%7}, {%8,%9}, {%0,%1,%2,%3};"
        : "+f"(c[0]), "+f"(c[1]), "+f"(c[2]), "+f"(c[3])
        : "r"(a[0]), "r"(a[1]), "r"(a[2]), "r"(a[3]), "r"(b[0]), "r"(b[1]));
}

// ---- cp.async helpers (LDGSTS: gmem->smem direct, no staging registers) ----
__device__ __forceinline__ void cpasync16(void* smem_ptr, const void* gmem_ptr) {
    u32 s = (u32)__cvta_generic_to_shared(smem_ptr);
    asm volatile("cp.async.cg.shared.global [%0], [%1], 16;" :: "r"(s), "l"(gmem_ptr));
}
__device__ __forceinline__ void cp_commit() {
    asm volatile("cp.async.commit_group;");
}

// ---- scratch (__device__ globals; no allocation allowed) ----
__device__ __align__(16) u16 g_hsh[MROWS * DD];
__device__ __align__(16) u16 g_hsl[MROWS * DD];
__device__ __align__(16) u16 g_wth[NQKV * DD];
__device__ __align__(16) u16 g_wtl[NQKV * DD];
__device__ __align__(16) u16 g_woth[DD * KO];
__device__ __align__(16) u16 g_wotl[DD * KO];
__device__ __align__(16) float g_qkv[MROWS * NQKV];
__device__ __align__(16) u16 g_ovhh[MROWS * KO];
__device__ __align__(16) u16 g_ovhl[MROWS * KO];
__device__ __align__(16) u16 g_qmh[BB * NH * SS * QKB];
__device__ __align__(16) u16 g_qml[BB * NH * SS * QKB];
__device__ __align__(16) float g_qc[BB * NH * SS];
__device__ __align__(16) u16 g_kh[BB * NKV * SS * QKB];
__device__ __align__(16) u16 g_kl[BB * NKV * SS * QKB];
__device__ __align__(16) u16 g_vth[BB * NKV * VB * SS];
__device__ __align__(16) u16 g_vtl[BB * NKV * VB * SS];

// ---------------------------------------------------------------------------
// Elementwise fp32 -> split bf16 (hi/lo). 8 elems/thread, all float4.
// ---------------------------------------------------------------------------
__global__ void convert_split_kernel(const float* __restrict__ src,
                                     u16* __restrict__ dh, u16* __restrict__ dl,
                                     int total)
{
    int idx = blockIdx.x * blockDim.x + threadIdx.x;
    int base = idx * 8;
    if (base >= total) return;
    float4 v0 = *(const float4*)(src + base);
    float4 v1 = *(const float4*)(src + base + 4);
    float xs[8] = {v0.x, v0.y, v0.z, v0.w, v1.x, v1.y, v1.z, v1.w};
    __align__(16) u32 oh[4];
    __align__(16) u32 ol[4];
#pragma unroll
    for (int i = 0; i < 4; i++) {
        float h0, l0, h1, l1;
        bsplit(xs[2 * i], h0, l0);
        bsplit(xs[2 * i + 1], h1, l1);
        oh[i] = packbf2(h0, h1);
        ol[i] = packbf2(l0, l1);
    }
    *(float4*)(dh + base) = *(float4*)&oh[0];
    *(float4*)(dl + base) = *(float4*)&ol[0];
}

// ---------------------------------------------------------------------------
// Transpose + split a weight: src fp32 [K][N] -> dst bf16 [nOff+n][K].
// ---------------------------------------------------------------------------
__global__ void __launch_bounds__(256) transpose_split_kernel(
    const float* __restrict__ src, int K, int N,
    u16* __restrict__ dh, u16* __restrict__ dl, int dstStride, int nOff)
{
    __shared__ __align__(16) float tile[32][33];
    const int n0 = blockIdx.x * 32;
    const int k0 = blockIdx.y * 32;
    const int t = threadIdx.x;
    {
        int r = t >> 3, c = (t & 7) * 4;
        float4 v = *(const float4*)(src + (size_t)(k0 + r) * N + n0 + c);
        tile[r][c + 0] = v.x; tile[r][c + 1] = v.y;
        tile[r][c + 2] = v.z; tile[r][c + 3] = v.w;
    }
    __syncthreads();
    {
        int col = t >> 3, k4 = (t & 7) * 4;
        __align__(8) u32 oh[2];
        __align__(8) u32 ol[2];
#pragma unroll
        for (int i = 0; i < 2; i++) {
            float h0, l0, h1, l1;
            bsplit(tile[k4 + 2 * i][col], h0, l0);
            bsplit(tile[k4 + 2 * i + 1][col], h1, l1);
            oh[i] = packbf2(h0, h1);
            ol[i] = packbf2(l0, l1);
        }
        size_t o = (size_t)(nOff + n0 + col) * dstStride + k0 + k4;
        *(float2*)(dh + o) = *(float2*)&oh[0];
        *(float2*)(dl + o) = *(float2*)&ol[0];
    }
}

// ---------------------------------------------------------------------------
// Split-bf16 tensor-core GEMM: C[M,N] = A[M,K] @ B^T (B stored [N][K]).
// Tile 128x64, K-step 16, 256 threads, warp tile 32x32, 3 MMAs per product.
// Double-buffered smem filled via cp.async (no staging registers).
// Row stride 24 u16 = 48B (16B multiple -> cp.async-16 aligned rows).
// ---------------------------------------------------------------------------
#define GPAD 24

template <int SIG>
__global__ void __launch_bounds__(256) bgemm_kernel(
    const u16* __restrict__ Ah, const u16* __restrict__ Al,
    const u16* __restrict__ Bh, const u16* __restrict__ Bl,
    float* __restrict__ C, int M, int N, int K)
{
    __shared__ __align__(16) u16 sAh[2][128][GPAD];
    __shared__ __align__(16) u16 sAl[2][128][GPAD];
    __shared__ __align__(16) u16 sBh[2][64][GPAD];
    __shared__ __align__(16) u16 sBl[2][64][GPAD];

    const int tid = threadIdx.x, warp = tid >> 5, lane = tid & 31;
    const int g = lane >> 2, tg = lane & 3;
    const int wm = warp >> 1, wn = warp & 1;
    const int row0 = blockIdx.y * 128, col0 = blockIdx.x * 64;

    // cp.async load coordinates: A 128 rows x 2 chunks (16B each) per array;
    // B 64 rows x 2 chunks, threads<128 do Bh, threads>=128 do Bl.
    const int lr = tid >> 1;              // A row 0..127
    const int lc = (tid & 1) * 8;         // u16 col 0 or 8
    const int brow = (tid & 127) >> 1;    // B row 0..63
    const int bc = (tid & 1) * 8;
    const bool doBh = tid < 128;

    #define BG_LOAD(st, k0_) do {                                                   \
        cpasync16(&sAh[st][lr][lc], Ah + (size_t)(row0 + lr) * K + (k0_) + lc);     \
        cpasync16(&sAl[st][lr][lc], Al + (size_t)(row0 + lr) * K + (k0_) + lc);     \
        if (doBh) cpasync16(&sBh[st][brow][bc],                                     \
                            Bh + (size_t)(col0 + brow) * K + (k0_) + bc);           \
        else      cpasync16(&sBl[st][brow][bc],                                     \
                            Bl + (size_t)(col0 + brow) * K + (k0_) + bc);           \
        cp_commit();                                                                \
    } while (0)

    float acc[2][4][4];
#pragma unroll
    for (int mt = 0; mt < 2; mt++)
#pragma unroll
        for (int nt = 0; nt < 4; nt++)
#pragma unroll
            for (int i = 0; i < 4; i++) acc[mt][nt][i] = 0.f;

    BG_LOAD(0, 0);

    int buf = 0;
    for (int k0 = 0; k0 < K; k0 += 16) {
        const bool more = (k0 + 16) < K;
        if (more) BG_LOAD(buf ^ 1, k0 + 16);

        if (more) asm volatile("cp.async.wait_group 1;");
        else      asm volatile("cp.async.wait_group 0;");
        __syncthreads();

        const int kb = tg * 2;
        u32 ah[2][4], al[2][4];
#pragma unroll
        for (int mt = 0; mt < 2; mt++) {
            int ar = wm * 32 + mt * 16 + g;
            ah[mt][0] = *(const u32*)&sAh[buf][ar][kb];
            ah[mt][1] = *(const u32*)&sAh[buf][ar + 8][kb];
            ah[mt][2] = *(const u32*)&sAh[buf][ar][kb + 8];
            ah[mt][3] = *(const u32*)&sAh[buf][ar + 8][kb + 8];
            al[mt][0] = *(const u32*)&sAl[buf][ar][kb];
            al[mt][1] = *(const u32*)&sAl[buf][ar + 8][kb];
            al[mt][2] = *(const u32*)&sAl[buf][ar][kb + 8];
            al[mt][3] = *(const u32*)&sAl[buf][ar + 8][kb + 8];
        }
#pragma unroll
        for (int nt = 0; nt < 4; nt++) {
            int br = wn * 32 + nt * 8 + g;
            u32 bh[2], bl[2];
            bh[0] = *(const u32*)&sBh[buf][br][kb];
            bh[1] = *(const u32*)&sBh[buf][br][kb + 8];
            bl[0] = *(const u32*)&sBl[buf][br][kb];
            bl[1] = *(const u32*)&sBl[buf][br][kb + 8];
#pragma unroll
            for (int mt = 0; mt < 2; mt++) {
                mma16816(acc[mt][nt], ah[mt], bh);
                mma16816(acc[mt][nt], ah[mt], bl);
                mma16816(acc[mt][nt], al[mt], bh);
            }
        }
        __syncthreads();   // protect buf^1 (overwritten by next iteration's cp.async)
        buf ^= 1;
    }
    #undef BG_LOAD

#pragma unroll
    for (int mt = 0; mt < 2; mt++) {
        int m0 = row0 + wm * 32 + mt * 16 + g;
#pragma unroll
        for (int nt = 0; nt < 4; nt++) {
            int n = col0 + wn * 32 + nt * 8 + tg * 2;
            float2 v0 = make_float2(acc[mt][nt][0], acc[mt][nt][1]);
            float2 v1 = make_float2(acc[mt][nt][2], acc[mt][nt][3]);
            if (SIG) {
                v0.x = 1.f / (1.f + __expf(-v0.x));
                v0.y = 1.f / (1.f + __expf(-v0.y));
                v1.x = 1.f / (1.f + __expf(-v1.x));
                v1.y = 1.f / (1.f + __expf(-v1.y));
            }
            *(float2*)&C[(size_t)m0 * N + n] = v0;
            *(float2*)&C[(size_t)(m0 + 8) * N + n] = v1;
        }
    }
}

// ---------------------------------------------------------------------------
// Convert Q/K rows (from the fused qkv buffer) to split-bf16 [b,head,s,16];
// for Q also apply 2x-1 and emit c = 16 - sum(pq).
// ---------------------------------------------------------------------------
template <bool ISQ>
__global__ void convqk_kernel(const float* __restrict__ src, int srcStride, int colOff,
                              u16* __restrict__ dh, u16* __restrict__ dl,
                              float* __restrict__ qc, int nheads)
{
    int tid = blockIdx.x * blockDim.x + threadIdx.x;
    int total = MROWS * nheads;
    if (tid >= total) return;
    int h = tid % nheads;
    int ms = tid / nheads;
    int b = ms / SS, s = ms - b * SS;

    const float4* p = (const float4*)(src + (size_t)ms * srcStride + colOff + h * QKB);
    float c = (float)QKB;
    __align__(16) u32 oh[8];
    __align__(16) u32 ol[8];
#pragma unroll
    for (int i = 0; i < 4; i++) {
        float4 v = p[i];
        float xs[4] = {v.x, v.y, v.z, v.w};
        float hs[4], ls[4];
#pragma unroll
        for (int j = 0; j < 4; j++) {
            float x = xs[j];
            if (ISQ) { c -= x; x = 2.f * x - 1.f; }
            bsplit(x, hs[j], ls[j]);
        }
        oh[i * 2]     = packbf2(hs[0], hs[1]);
        oh[i * 2 + 1] = packbf2(hs[2], hs[3]);
        ol[i * 2]     = packbf2(ls[0], ls[1]);
        ol[i * 2 + 1] = packbf2(ls[2], ls[3]);
    }
    size_t orow = ((size_t)(b * nheads + h) * SS + s) * QKB;
    ((float4*)(dh + orow))[0] = *(float4*)&oh[0];
    ((float4*)(dh + orow))[1] = *(float4*)&oh[4];
    ((float4*)(dl + orow))[0] = *(float4*)&ol[0];
    ((float4*)(dl + orow))[1] = *(float4*)&ol[4];
    if (ISQ) qc[(size_t)(b * nheads + h) * SS + s] = c;
}

// ---------------------------------------------------------------------------
// Transpose + split V (from qkv buffer) -> [b,kv,vd,S] bf16 hi/lo.
// ---------------------------------------------------------------------------
#define VOFF (NH * QKB + NKV * QKB)   // 320

__global__ void __launch_bounds__(256) convv_kernel(
    const float* __restrict__ qkv, u16* __restrict__ vth, u16* __restrict__ vtl)
{
    __shared__ __align__(16) float tile[64][33];
    const int s0 = blockIdx.x * 64;
    const int kv = blockIdx.y;
    const int b  = blockIdx.z;
    const int t  = threadIdx.x;

    {
        int sl = t >> 2, vg = (t & 3) * 8;
        const float4* src = (const float4*)(qkv + ((size_t)(b * SS + s0 + sl)) * NQKV
                                            + VOFF + kv * VB + vg);
        float4 v0 = src[0], v1 = src[1];
        tile[sl][vg + 0] = v0.x; tile[sl][vg + 1] = v0.y;
        tile[sl][vg + 2] = v0.z; tile[sl][vg + 3] = v0.w;
        tile[sl][vg + 4] = v1.x; tile[sl][vg + 5] = v1.y;
        tile[sl][vg + 6] = v1.z; tile[sl][vg + 7] = v1.w;
    }
    __syncthreads();
    {
        int vd = t >> 3, sc = (t & 7) * 8;
        __align__(16) u32 oh[4];
        __align__(16) u32 ol[4];
#pragma unroll
        for (int j = 0; j < 4; j++) {
            float x0 = tile[sc + 2 * j][vd], x1 = tile[sc + 2 * j + 1][vd];
            float h0, l0, h1, l1;
            bsplit(x0, h0, l0); bsplit(x1, h1, l1);
            oh[j] = packbf2(h0, h1);
            ol[j] = packbf2(l0, l1);
        }
        size_t orow = (((size_t)(b * NKV + kv) * VB + vd) * SS) + s0 + sc;
        *(float4*)(vth + orow) = *(float4*)&oh[0];
        *(float4*)(vtl + orow) = *(float4*)&ol[0];
    }
}

// ---------------------------------------------------------------------------
// Flash-style causal attention on tensor cores (mma.sync bf16, hi/lo split).
// (LPT ordering reverted — measured neutral/regressive in R11.)
// ---------------------------------------------------------------------------
#define QM 128
#define BN 128
#define SKP 24
#define SVP (BN + 8)

__global__ void __launch_bounds__(256) rosa_attn_mma(
    const u16* __restrict__ qmh, const u16* __restrict__ qml,
    const float* __restrict__ qc,
    const u16* __restrict__ kh, const u16* __restrict__ kl,
    const u16* __restrict__ vth, const u16* __restrict__ vtl,
    const float* __restrict__ e0, const float* __restrict__ e1,
    u16* __restrict__ ovhh, u16* __restrict__ ovhl)
{
    __shared__ __align__(16) u16 skh[BN][SKP];
    __shared__ __align__(16) u16 skl[BN][SKP];
    __shared__ __align__(16) u16 svh[VB][SVP];
    __shared__ __align__(16) u16 svl[VB][SVP];

    const int qblk = blockIdx.x;
    const int h = blockIdx.y, b = blockIdx.z;
    const int kv = h / NREP;
    const int tid = threadIdx.x, warp = tid >> 5, lane = tid & 31;
    const int g = lane >> 2, tg = lane & 3;
    const int qw0 = qblk * QM + warp * 16;

    const u16* qbh = qmh + ((size_t)(b * NH + h) * SS) * QKB;
    const u16* qbl = qml + ((size_t)(b * NH + h) * SS) * QKB;
    size_t a0 = (size_t)(qw0 + g) * QKB + tg * 2;
    u32 a_hi[4], a_lo[4];
    a_hi[0] = *(const u32*)(qbh + a0);
    a_hi[1] = *(const u32*)(qbh + a0 + 8 * QKB);
    a_hi[2] = *(const u32*)(qbh + a0 + 8);
    a_hi[3] = *(const u32*)(qbh + a0 + 8 * QKB + 8);
    a_lo[0] = *(const u32*)(qbl + a0);
    a_lo[1] = *(const u32*)(qbl + a0 + 8 * QKB);
    a_lo[2] = *(const u32*)(qbl + a0 + 8);
    a_lo[3] = *(const u32*)(qbl + a0 + 8 * QKB + 8);
    const float* qcb = qc + (size_t)(b * NH + h) * SS + qw0;
    const float c0 = qcb[g], c1 = qcb[g + 8];
    const int qg0 = qw0 + g, qg1 = qg0 + 8;

    float num[4][4];
#pragma unroll
    for (int i = 0; i < 4; i++)
#pragma unroll
        for (int j = 0; j < 4; j++) num[i][j] = 0.f;
    float den0 = 0.f, den1 = 0.f;

    const u16* kbh = kh + ((size_t)(b * NKV + kv) * SS) * QKB;
    const u16* kbl = kl + ((size_t)(b * NKV + kv) * SS) * QKB;
    const u16* vbh = vth + ((size_t)(b * NKV + kv) * VB) * SS;
    const u16* vbl = vtl + ((size_t)(b * NKV + kv) * VB) * SS;

    for (int t0 = 0; t0 <= qblk; t0++) {
        {
            int r = tid & 127;
            const u16* src = ((tid < 128) ? kbh : kbl) + ((size_t)(t0 * BN + r)) * QKB;
            u16 (*dst)[SKP] = (tid < 128) ? skh : skl;
            float4 v0 = ((const float4*)src)[0];
            float4 v1 = ((const float4*)src)[1];
            *(float4*)&dst[r][0] = v0;
            *(float4*)&dst[r][8] = v1;
        }
#pragma unroll
        for (int i = 0; i < 2; i++) {
            int idx = tid + i * 256;
            int row = idx >> 4, c4 = idx & 15;
            *(float4*)&svh[row][c4 * 8] =
                *((const float4*)(vbh + (size_t)row * SS + t0 * BN) + c4);
            *(float4*)&svl[row][c4 * 8] =
                *((const float4*)(vbl + (size_t)row * SS + t0 * BN) + c4);
        }
        __syncthreads();

        const bool diag = (t0 == qblk);
        for (int kc = 0; kc < 8; kc++) {
            float sc[2][4];
#pragma unroll
            for (int hf = 0; hf < 2; hf++) {
                int n8 = kc * 16 + hf * 8;
                u32 bh_[2], bl_[2];
                const u16* kr  = &skh[n8 + g][tg * 2];
                const u16* krl = &skl[n8 + g][tg * 2];
                bh_[0] = *(const u32*)kr;        bh_[1] = *(const u32*)(kr + 8);
                bl_[0] = *(const u32*)krl;       bl_[1] = *(const u32*)(krl + 8);
                float cc[4] = {0.f, 0.f, 0.f, 0.f};
                mma16816(cc, a_hi, bh_);
                mma16816(cc, a_hi, bl_);
                mma16816(cc, a_lo, bh_);
                sc[hf][0] = cc[0]; sc[hf][1] = cc[1];
                sc[hf][2] = cc[2]; sc[hf][3] = cc[3];
            }
            u32 Ah[4], Al[4];
#pragma unroll
            for (int hf = 0; hf < 2; hf++) {
                int kb = t0 * BN + kc * 16 + hf * 8 + tg * 2;
                float p0 = __expf(sc[hf][0] + c0);
                float p1 = __expf(sc[hf][1] + c0);
                float p2 = __expf(sc[hf][2] + c1);
                float p3 = __expf(sc[hf][3] + c1);
                if (diag) {
                    if (kb     > qg0) p0 = 0.f;
                    if (kb + 1 > qg0) p1 = 0.f;
                    if (kb     > qg1) p2 = 0.f;
                    if (kb + 1 > qg1) p3 = 0.f;
                }
                den0 += p0 + p1;
                den1 += p2 + p3;
                float h0, l0, h1, l1, h2, l2, h3, l3;
                bsplit(p0, h0, l0); bsplit(p1, h1, l1);
                bsplit(p2, h2, l2); bsplit(p3, h3, l3);
                Ah[hf * 2]     = packbf2(h0, h1);
                Ah[hf * 2 + 1] = packbf2(h2, h3);
                Al[hf * 2]     = packbf2(l0, l1);
                Al[hf * 2 + 1] = packbf2(l2, l3);
            }
#pragma unroll
            for (int vt = 0; vt < 4; vt++) {
                u32 bvh[2], bvl[2];
                const u16* vr  = &svh[vt * 8 + g][kc * 16 + tg * 2];
                const u16* vrl = &svl[vt * 8 + g][kc * 16 + tg * 2];
                bvh[0] = *(const u32*)vr;   bvh[1] = *(const u32*)(vr + 8);
                bvl[0] = *(const u32*)vrl;  bvl[1] = *(const u32*)(vrl + 8);
                mma16816(num[vt], Ah, bvh);
                mma16816(num[vt], Ah, bvl);
                mma16816(num[vt], Al, bvh);
            }
        }
        __syncthreads();
    }

    den0 += __shfl_xor_sync(0xffffffffu, den0, 1);
    den0 += __shfl_xor_sync(0xffffffffu, den0, 2);
    den1 += __shfl_xor_sync(0xffffffffu, den1, 1);
    den1 += __shfl_xor_sync(0xffffffffu, den1, 2);
    const float inv0 = 1.f / den0, inv1 = 1.f / den1;

#pragma unroll
    for (int vt = 0; vt < 4; vt++) {
        int vd = vt * 8 + tg * 2;
        float a00 = e0[h * VB + vd],     b00 = e1[h * VB + vd];
        float a01 = e0[h * VB + vd + 1], b01 = e1[h * VB + vd + 1];
        float o00 = fmaf(b00 - a00, num[vt][0] * inv0, a00);
        float o01 = fmaf(b01 - a01, num[vt][1] * inv0, a01);
        float o10 = fmaf(b00 - a00, num[vt][2] * inv1, a00);
        float o11 = fmaf(b01 - a01, num[vt][3] * inv1, a01);
        float h0, l0, h1, l1;
        size_t i0 = ((size_t)(b * SS + qg0) * NH + h) * VB + vd;
        size_t i1 = ((size_t)(b * SS + qg1) * NH + h) * VB + vd;
        bsplit(o00, h0, l0); bsplit(o01, h1, l1);
        *(u32*)&ovhh[i0] = packbf2(h0, h1);
        *(u32*)&ovhl[i0] = packbf2(l0, l1);
        bsplit(o10, h0, l0); bsplit(o11, h1, l1);
        *(u32*)&ovhh[i1] = packbf2(h0, h1);
        *(u32*)&ovhl[i1] = packbf2(l0, l1);
    }
}

// ---------------------------------------------------------------------------
extern "C" void kernel_launch(void* const* d_in, const int* in_sizes, int n_in,
                              void* d_out, int out_size)
{
    const float* hs = (const float*)d_in[0];
    const float* Wq = (const float*)d_in[1];
    const float* Wk = (const float*)d_in[2];
    const float* Wv = (const float*)d_in[3];
    const float* Wo = (const float*)d_in[4];
    const float* e0 = (const float*)d_in[5];
    const float* e1 = (const float*)d_in[6];
    float* out = (float*)d_out;

    u16 *hsh, *hsl, *wth, *wtl, *woth, *wotl, *ovhh, *ovhl;
    u16 *qmh, *qml, *kh_, *kl_, *vth, *vtl;
    float *qkv, *qcp;
    cudaGetSymbolAddress((void**)&hsh,  g_hsh);
    cudaGetSymbolAddress((void**)&hsl,  g_hsl);
    cudaGetSymbolAddress((void**)&wth,  g_wth);
    cudaGetSymbolAddress((void**)&wtl,  g_wtl);
    cudaGetSymbolAddress((void**)&woth, g_woth);
    cudaGetSymbolAddress((void**)&wotl, g_wotl);
    cudaGetSymbolAddress((void**)&qkv,  g_qkv);
    cudaGetSymbolAddress((void**)&ovhh, g_ovhh);
    cudaGetSymbolAddress((void**)&ovhl, g_ovhl);
    cudaGetSymbolAddress((void**)&qcp,  g_qc);
    cudaGetSymbolAddress((void**)&qmh,  g_qmh);
    cudaGetSymbolAddress((void**)&qml,  g_qml);
    cudaGetSymbolAddress((void**)&kh_,  g_kh);
    cudaGetSymbolAddress((void**)&kl_,  g_kl);
    cudaGetSymbolAddress((void**)&vth,  g_vth);
    cudaGetSymbolAddress((void**)&vtl,  g_vtl);

    convert_split_kernel<<<(MROWS * DD / 8 + 255) / 256, 256>>>(hs, hsh, hsl, MROWS * DD);
    transpose_split_kernel<<<dim3(256 / 32, DD / 32), 256>>>(Wq, DD, 256, wth, wtl, DD, 0);
    transpose_split_kernel<<<dim3(64 / 32,  DD / 32), 256>>>(Wk, DD, 64,  wth, wtl, DD, 256);
    transpose_split_kernel<<<dim3(128 / 32, DD / 32), 256>>>(Wv, DD, 128, wth, wtl, DD, 320);
    transpose_split_kernel<<<dim3(DD / 32,  KO / 32), 256>>>(Wo, KO, DD,  woth, wotl, KO, 0);

    bgemm_kernel<1><<<dim3(NQKV / 64, MROWS / 128), 256>>>(
        hsh, hsl, wth, wtl, qkv, MROWS, NQKV, DD);

    convqk_kernel<true ><<<(MROWS * NH  + 127) / 128, 128>>>(qkv, NQKV, 0,   qmh, qml, qcp, NH);
    convqk_kernel<false><<<(MROWS * NKV + 127) / 128, 128>>>(qkv, NQKV, 256, kh_, kl_, nullptr, NKV);
    convv_kernel<<<dim3(SS / 64, NKV, BB), 256>>>(qkv, vth, vtl);

    rosa_attn_mma<<<dim3(SS / QM, NH, BB), 256>>>(qmh, qml, qcp, kh_, kl_, vth, vtl,
                                                  e0, e1, ovhh, ovhl);

    bgemm_kernel<0><<<dim3(DD / 64, MROWS / 128), 256>>>(
        ovhh, ovhl, woth, wotl, out, MROWS, DD, KO);
}

// round 17
// speedup vs baseline: 1.6664x; 1.0261x over previous
#include <cuda_runtime.h>
#include <cuda_bf16.h>
#include <cuda_fp16.h>
#include <math.h>

#define BB 2
#define SS 2048
#define DD 1024
#define NH 16
#define NKV 4
#define QKB 16
#define VB 32
#define NREP (NH / NKV)
#define MROWS (BB * SS)       // 4096
#define NQKV (NH * QKB + NKV * QKB + NKV * VB)   // 448
#define KO (NH * VB)          // 512
#define OSC 1048576.f         // Wo' pre-scale (2^20, exact power of two)

typedef unsigned int u32;
typedef unsigned short u16;

// ---- bf16 split helpers ----
__device__ __forceinline__ void bsplit(float x, float& hi, float& lo) {
    float h = __bfloat162float(__float2bfloat16(x));
    hi = h; lo = x - h;
}
__device__ __forceinline__ u32 packbf2(float a, float b) {   // a -> low half
    __nv_bfloat162 t = __floats2bfloat162_rn(a, b);
    return *(u32*)&t;
}
// ---- fp16 split helpers (O-projection path) ----
__device__ __forceinline__ void hsplit(float x, float& hi, float& lo) {
    float h = __half2float(__float2half_rn(x));
    hi = h; lo = x - h;
}
__device__ __forceinline__ u32 packh2(float a, float b) {    // a -> low half
    __half2 t = __floats2half2_rn(a, b);
    return *(u32*)&t;
}

// ---- mma.sync m16n8k16, f32 accum: bf16 and fp16 flavors ----
__device__ __forceinline__ void mma16816(float c[4], const u32 a[4], const u32 b[2]) {
    asm volatile(
        "mma.sync.aligned.m16n8k16.row.col.f32.bf16.bf16.f32 "
        "{%0,%1,%2,%3}, {%4,%5,%6,%7}, {%8,%9}, {%0,%1,%2,%3};"
        : "+f"(c[0]), "+f"(c[1]), "+f"(c[2]), "+f"(c[3])
        : "r"(a[0]), "r"(a[1]), "r"(a[2]), "r"(a[3]), "r"(b[0]), "r"(b[1]));
}
__device__ __forceinline__ void mma16816h(float c[4], const u32 a[4], const u32 b[2]) {
    asm volatile(
        "mma.sync.aligned.m16n8k16.row.col.f32.f16.f16.f32 "
        "{%0,%1,%2,%3}, {%4,%5,%6,%7}, {%8,%9}, {%0,%1,%2,%3};"
        : "+f"(c[0]), "+f"(c[1]), "+f"(c[2]), "+f"(c[3])
        : "r"(a[0]), "r"(a[1]), "r"(a[2]), "r"(a[3]), "r"(b[0]), "r"(b[1]));
}

// ---- scratch (__device__ globals; no allocation allowed) ----
__device__ __align__(16) u16 g_hsh[MROWS * DD];
__device__ __align__(16) u16 g_hsl[MROWS * DD];
__device__ __align__(16) u16 g_wth[NQKV * DD];
__device__ __align__(16) u16 g_wtl[NQKV * DD];
__device__ __align__(16) u16 g_woth[DD * KO];     // fp16 scaled Wo' hi
__device__ __align__(16) u16 g_wotl[DD * KO];     //                 lo
__device__ __align__(16) float g_qkv[MROWS * NQKV];
__device__ __align__(16) u16 g_tvh[MROWS * KO];   // fp16 t = 2vh-1
__device__ __align__(16) float g_cvec[DD];
__device__ __align__(16) u16 g_qmh[BB * NH * SS * QKB];
__device__ __align__(16) u16 g_qml[BB * NH * SS * QKB];
__device__ __align__(16) float g_qc[BB * NH * SS];
__device__ __align__(16) u16 g_kh[BB * NKV * SS * QKB];
__device__ __align__(16) u16 g_kl[BB * NKV * SS * QKB];
__device__ __align__(16) u16 g_vth[BB * NKV * VB * SS];
__device__ __align__(16) u16 g_vtl[BB * NKV * VB * SS];

// ---------------------------------------------------------------------------
// Elementwise fp32 -> split bf16 (hi/lo). 8 elems/thread, all float4.
// ---------------------------------------------------------------------------
__global__ void convert_split_kernel(const float* __restrict__ src,
                                     u16* __restrict__ dh, u16* __restrict__ dl,
                                     int total)
{
    int idx = blockIdx.x * blockDim.x + threadIdx.x;
    int base = idx * 8;
    if (base >= total) return;
    float4 v0 = *(const float4*)(src + base);
    float4 v1 = *(const float4*)(src + base + 4);
    float xs[8] = {v0.x, v0.y, v0.z, v0.w, v1.x, v1.y, v1.z, v1.w};
    __align__(16) u32 oh[4];
    __align__(16) u32 ol[4];
#pragma unroll
    for (int i = 0; i < 4; i++) {
        float h0, l0, h1, l1;
        bsplit(xs[2 * i], h0, l0);
        bsplit(xs[2 * i + 1], h1, l1);
        oh[i] = packbf2(h0, h1);
        ol[i] = packbf2(l0, l1);
    }
    *(float4*)(dh + base) = *(float4*)&oh[0];
    *(float4*)(dl + base) = *(float4*)&ol[0];
}

// ---------------------------------------------------------------------------
// cvec[n] = sum_k 0.5*(e0[k]+e1[k]) * Wo[k][n]
// ---------------------------------------------------------------------------
__global__ void cvec_kernel(const float* __restrict__ Wo,
                            const float* __restrict__ e0,
                            const float* __restrict__ e1,
                            float* __restrict__ cvec)
{
    int n = blockIdx.x * blockDim.x + threadIdx.x;
    if (n >= DD) return;
    float s = 0.f;
    for (int k = 0; k < KO; k++)
        s += 0.5f * (e0[k] + e1[k]) * Wo[(size_t)k * DD + n];
    cvec[n] = s;
}

// ---------------------------------------------------------------------------
// Transpose + split a weight: src fp32 [K][N] -> dst [nOff+n][K].
// MODE 0: bf16 split (QKV weights).
// MODE 1: fp16 split, row-scaled by 0.5*(e1[k]-e0[k])*OSC (Wo').
// ---------------------------------------------------------------------------
template <int MODE>
__global__ void __launch_bounds__(256) transpose_split_kernel(
    const float* __restrict__ src, int K, int N,
    u16* __restrict__ dh, u16* __restrict__ dl, int dstStride, int nOff,
    const float* __restrict__ se0, const float* __restrict__ se1)
{
    __shared__ __align__(16) float tile[32][33];
    const int n0 = blockIdx.x * 32;
    const int k0 = blockIdx.y * 32;
    const int t = threadIdx.x;
    {
        int r = t >> 3, c = (t & 7) * 4;
        float4 v = *(const float4*)(src + (size_t)(k0 + r) * N + n0 + c);
        tile[r][c + 0] = v.x; tile[r][c + 1] = v.y;
        tile[r][c + 2] = v.z; tile[r][c + 3] = v.w;
    }
    __syncthreads();
    {
        int col = t >> 3, k4 = (t & 7) * 4;
        __align__(8) u32 oh[2];
        __align__(8) u32 ol[2];
#pragma unroll
        for (int i = 0; i < 2; i++) {
            int ka = k0 + k4 + 2 * i;
            float x0 = tile[k4 + 2 * i][col];
            float x1 = tile[k4 + 2 * i + 1][col];
            float h0, l0, h1, l1;
            if (MODE == 1) {
                x0 *= 0.5f * (se1[ka] - se0[ka]) * OSC;
                x1 *= 0.5f * (se1[ka + 1] - se0[ka + 1]) * OSC;
                hsplit(x0, h0, l0); hsplit(x1, h1, l1);
                oh[i] = packh2(h0, h1);
                ol[i] = packh2(l0, l1);
            } else {
                bsplit(x0, h0, l0); bsplit(x1, h1, l1);
                oh[i] = packbf2(h0, h1);
                ol[i] = packbf2(l0, l1);
            }
        }
        size_t o = (size_t)(nOff + n0 + col) * dstStride + k0 + k4;
        *(float2*)(dh + o) = *(float2*)&oh[0];
        *(float2*)(dl + o) = *(float2*)&ol[0];
    }
}

// ---------------------------------------------------------------------------
// Split-bf16 GEMM (QKV): C = A @ B^T, 3 MMAs/product, sigmoid epilogue.
// Exact R8 version (verified at 280.6 us total).
// ---------------------------------------------------------------------------
__global__ void __launch_bounds__(256) bgemm_kernel(
    const u16* __restrict__ Ah, const u16* __restrict__ Al,
    const u16* __restrict__ Bh, const u16* __restrict__ Bl,
    float* __restrict__ C, int M, int N, int K)
{
    __shared__ __align__(16) u16 sAh[128][40];
    __shared__ __align__(16) u16 sAl[128][40];
    __shared__ __align__(16) u16 sBh[64][40];
    __shared__ __align__(16) u16 sBl[64][40];

    const int tid = threadIdx.x, warp = tid >> 5, lane = tid & 31;
    const int g = lane >> 2, tg = lane & 3;
    const int wm = warp >> 1, wn = warp & 1;
    const int row0 = blockIdx.y * 128, col0 = blockIdx.x * 64;

    float acc[2][4][4];
#pragma unroll
    for (int mt = 0; mt < 2; mt++)
#pragma unroll
        for (int nt = 0; nt < 4; nt++)
#pragma unroll
            for (int i = 0; i < 4; i++) acc[mt][nt][i] = 0.f;

    for (int k0 = 0; k0 < K; k0 += 32) {
#pragma unroll
        for (int i = 0; i < 2; i++) {
            int ch = tid + i * 256;
            int r = ch >> 2, c = (ch & 3) * 8;
            *(float4*)&sAh[r][c] = *(const float4*)(Ah + (size_t)(row0 + r) * K + k0 + c);
            *(float4*)&sAl[r][c] = *(const float4*)(Al + (size_t)(row0 + r) * K + k0 + c);
        }
        {
            int r = tid >> 2, c = (tid & 3) * 8;
            *(float4*)&sBh[r][c] = *(const float4*)(Bh + (size_t)(col0 + r) * K + k0 + c);
            *(float4*)&sBl[r][c] = *(const float4*)(Bl + (size_t)(col0 + r) * K + k0 + c);
        }
        __syncthreads();

#pragma unroll
        for (int k16 = 0; k16 < 2; k16++) {
            const int kb = k16 * 16 + tg * 2;
            u32 ah[2][4], al[2][4];
#pragma unroll
            for (int mt = 0; mt < 2; mt++) {
                int ar = wm * 32 + mt * 16 + g;
                ah[mt][0] = *(const u32*)&sAh[ar][kb];
                ah[mt][1] = *(const u32*)&sAh[ar + 8][kb];
                ah[mt][2] = *(const u32*)&sAh[ar][kb + 8];
                ah[mt][3] = *(const u32*)&sAh[ar + 8][kb + 8];
                al[mt][0] = *(const u32*)&sAl[ar][kb];
                al[mt][1] = *(const u32*)&sAl[ar + 8][kb];
                al[mt][2] = *(const u32*)&sAl[ar][kb + 8];
                al[mt][3] = *(const u32*)&sAl[ar + 8][kb + 8];
            }
#pragma unroll
            for (int nt = 0; nt < 4; nt++) {
                int br = wn * 32 + nt * 8 + g;
                u32 bh[2], bl[2];
                bh[0] = *(const u32*)&sBh[br][kb];
                bh[1] = *(const u32*)&sBh[br][kb + 8];
                bl[0] = *(const u32*)&sBl[br][kb];
                bl[1] = *(const u32*)&sBl[br][kb + 8];
#pragma unroll
                for (int mt = 0; mt < 2; mt++) {
                    mma16816(acc[mt][nt], ah[mt], bh);
                    mma16816(acc[mt][nt], ah[mt], bl);
                    mma16816(acc[mt][nt], al[mt], bh);
                }
            }
        }
        __syncthreads();
    }

#pragma unroll
    for (int mt = 0; mt < 2; mt++) {
        int m0 = row0 + wm * 32 + mt * 16 + g;
#pragma unroll
        for (int nt = 0; nt < 4; nt++) {
            int n = col0 + wn * 32 + nt * 8 + tg * 2;
            float2 v0 = make_float2(acc[mt][nt][0], acc[mt][nt][1]);
            float2 v1 = make_float2(acc[mt][nt][2], acc[mt][nt][3]);
            v0.x = 1.f / (1.f + __expf(-v0.x));
            v0.y = 1.f / (1.f + __expf(-v0.y));
            v1.x = 1.f / (1.f + __expf(-v1.x));
            v1.y = 1.f / (1.f + __expf(-v1.y));
            *(float2*)&C[(size_t)m0 * N + n] = v0;
            *(float2*)&C[(size_t)(m0 + 8) * N + n] = v1;
        }
    }
}

// ---------------------------------------------------------------------------
// O-projection GEMM (fp16): out[m][n] = cvec[n] + (A @ B'^T)[m][n] / OSC
// A = t = (2vh-1) single fp16 [M][K]; B' = scaled Wo' split fp16 [N][K].
// 2 MMAs per product (A*Bh + A*Bl); A-residual dropped (rel ~2.8e-4).
// ---------------------------------------------------------------------------
__global__ void __launch_bounds__(256) bgemm_o(
    const u16* __restrict__ Ax,
    const u16* __restrict__ Bh, const u16* __restrict__ Bl,
    const float* __restrict__ cvec,
    float* __restrict__ C, int M, int N, int K)
{
    __shared__ __align__(16) u16 sA[128][40];
    __shared__ __align__(16) u16 sBh[64][40];
    __shared__ __align__(16) u16 sBl[64][40];

    const int tid = threadIdx.x, warp = tid >> 5, lane = tid & 31;
    const int g = lane >> 2, tg = lane & 3;
    const int wm = warp >> 1, wn = warp & 1;
    const int row0 = blockIdx.y * 128, col0 = blockIdx.x * 64;

    float acc[2][4][4];
#pragma unroll
    for (int mt = 0; mt < 2; mt++)
#pragma unroll
        for (int nt = 0; nt < 4; nt++)
#pragma unroll
            for (int i = 0; i < 4; i++) acc[mt][nt][i] = 0.f;

    for (int k0 = 0; k0 < K; k0 += 32) {
#pragma unroll
        for (int i = 0; i < 2; i++) {      // A tile: 128 x 32 halves
            int ch = tid + i * 256;
            int r = ch >> 2, c = (ch & 3) * 8;
            *(float4*)&sA[r][c] = *(const float4*)(Ax + (size_t)(row0 + r) * K + k0 + c);
        }
        {                                   // B tiles: 64 x 32 halves each
            int r = tid >> 2, c = (tid & 3) * 8;
            *(float4*)&sBh[r][c] = *(const float4*)(Bh + (size_t)(col0 + r) * K + k0 + c);
            *(float4*)&sBl[r][c] = *(const float4*)(Bl + (size_t)(col0 + r) * K + k0 + c);
        }
        __syncthreads();

#pragma unroll
        for (int k16 = 0; k16 < 2; k16++) {
            const int kb = k16 * 16 + tg * 2;
            u32 ah[2][4];
#pragma unroll
            for (int mt = 0; mt < 2; mt++) {
                int ar = wm * 32 + mt * 16 + g;
                ah[mt][0] = *(const u32*)&sA[ar][kb];
                ah[mt][1] = *(const u32*)&sA[ar + 8][kb];
                ah[mt][2] = *(const u32*)&sA[ar][kb + 8];
                ah[mt][3] = *(const u32*)&sA[ar + 8][kb + 8];
            }
#pragma unroll
            for (int nt = 0; nt < 4; nt++) {
                int br = wn * 32 + nt * 8 + g;
                u32 bh[2], bl[2];
                bh[0] = *(const u32*)&sBh[br][kb];
                bh[1] = *(const u32*)&sBh[br][kb + 8];
                bl[0] = *(const u32*)&sBl[br][kb];
                bl[1] = *(const u32*)&sBl[br][kb + 8];
#pragma unroll
                for (int mt = 0; mt < 2; mt++) {
                    mma16816h(acc[mt][nt], ah[mt], bh);
                    mma16816h(acc[mt][nt], ah[mt], bl);
                }
            }
        }
        __syncthreads();
    }

    const float isc = 1.f / OSC;
#pragma unroll
    for (int mt = 0; mt < 2; mt++) {
        int m0 = row0 + wm * 32 + mt * 16 + g;
#pragma unroll
        for (int nt = 0; nt < 4; nt++) {
            int n = col0 + wn * 32 + nt * 8 + tg * 2;
            float cv0 = cvec[n], cv1 = cvec[n + 1];
            float2 v0 = make_float2(fmaf(acc[mt][nt][0], isc, cv0),
                                    fmaf(acc[mt][nt][1], isc, cv1));
            float2 v1 = make_float2(fmaf(acc[mt][nt][2], isc, cv0),
                                    fmaf(acc[mt][nt][3], isc, cv1));
            *(float2*)&C[(size_t)m0 * N + n] = v0;
            *(float2*)&C[(size_t)(m0 + 8) * N + n] = v1;
        }
    }
}

// ---------------------------------------------------------------------------
// Convert Q/K rows (from the fused qkv buffer) to split-bf16 [b,head,s,16];
// for Q also apply 2x-1 and emit c = 16 - sum(pq).
// ---------------------------------------------------------------------------
template <bool ISQ>
__global__ void convqk_kernel(const float* __restrict__ src, int srcStride, int colOff,
                              u16* __restrict__ dh, u16* __restrict__ dl,
                              float* __restrict__ qc, int nheads)
{
    int tid = blockIdx.x * blockDim.x + threadIdx.x;
    int total = MROWS * nheads;
    if (tid >= total) return;
    int h = tid % nheads;
    int ms = tid / nheads;
    int b = ms / SS, s = ms - b * SS;

    const float4* p = (const float4*)(src + (size_t)ms * srcStride + colOff + h * QKB);
    float c = (float)QKB;
    __align__(16) u32 oh[8];
    __align__(16) u32 ol[8];
#pragma unroll
    for (int i = 0; i < 4; i++) {
        float4 v = p[i];
        float xs[4] = {v.x, v.y, v.z, v.w};
        float hs[4], ls[4];
#pragma unroll
        for (int j = 0; j < 4; j++) {
            float x = xs[j];
            if (ISQ) { c -= x; x = 2.f * x - 1.f; }
            bsplit(x, hs[j], ls[j]);
        }
        oh[i * 2]     = packbf2(hs[0], hs[1]);
        oh[i * 2 + 1] = packbf2(hs[2], hs[3]);
        ol[i * 2]     = packbf2(ls[0], ls[1]);
        ol[i * 2 + 1] = packbf2(ls[2], ls[3]);
    }
    size_t orow = ((size_t)(b * nheads + h) * SS + s) * QKB;
    ((float4*)(dh + orow))[0] = *(float4*)&oh[0];
    ((float4*)(dh + orow))[1] = *(float4*)&oh[4];
    ((float4*)(dl + orow))[0] = *(float4*)&ol[0];
    ((float4*)(dl + orow))[1] = *(float4*)&ol[4];
    if (ISQ) qc[(size_t)(b * nheads + h) * SS + s] = c;
}

// ---------------------------------------------------------------------------
// Transpose + split V (from qkv buffer) -> [b,kv,vd,S] bf16 hi/lo.
// ---------------------------------------------------------------------------
#define VOFF (NH * QKB + NKV * QKB)   // 320

__global__ void __launch_bounds__(256) convv_kernel(
    const float* __restrict__ qkv, u16* __restrict__ vth, u16* __restrict__ vtl)
{
    __shared__ __align__(16) float tile[64][33];
    const int s0 = blockIdx.x * 64;
    const int kv = blockIdx.y;
    const int b  = blockIdx.z;
    const int t  = threadIdx.x;

    {
        int sl = t >> 2, vg = (t & 3) * 8;
        const float4* src = (const float4*)(qkv + ((size_t)(b * SS + s0 + sl)) * NQKV
                                            + VOFF + kv * VB + vg);
        float4 v0 = src[0], v1 = src[1];
        tile[sl][vg + 0] = v0.x; tile[sl][vg + 1] = v0.y;
        tile[sl][vg + 2] = v0.z; tile[sl][vg + 3] = v0.w;
        tile[sl][vg + 4] = v1.x; tile[sl][vg + 5] = v1.y;
        tile[sl][vg + 6] = v1.z; tile[sl][vg + 7] = v1.w;
    }
    __syncthreads();
    {
        int vd = t >> 3, sc = (t & 7) * 8;
        __align__(16) u32 oh[4];
        __align__(16) u32 ol[4];
#pragma unroll
        for (int j = 0; j < 4; j++) {
            float x0 = tile[sc + 2 * j][vd], x1 = tile[sc + 2 * j + 1][vd];
            float h0, l0, h1, l1;
            bsplit(x0, h0, l0); bsplit(x1, h1, l1);
            oh[j] = packbf2(h0, h1);
            ol[j] = packbf2(l0, l1);
        }
        size_t orow = (((size_t)(b * NKV + kv) * VB + vd) * SS) + s0 + sc;
        *(float4*)(vth + orow) = *(float4*)&oh[0];
        *(float4*)(vtl + orow) = *(float4*)&ol[0];
    }
}

// ---------------------------------------------------------------------------
// Flash-style causal attention on tensor cores (mma.sync bf16, hi/lo split).
// Epilogue emits t = 2*vh - 1 as single fp16 for the O-projection GEMM.
// ---------------------------------------------------------------------------
#define QM 128
#define BN 128
#define SKP 24
#define SVP (BN + 8)

__global__ void __launch_bounds__(256) rosa_attn_mma(
    const u16* __restrict__ qmh, const u16* __restrict__ qml,
    const float* __restrict__ qc,
    const u16* __restrict__ kh, const u16* __restrict__ kl,
    const u16* __restrict__ vth, const u16* __restrict__ vtl,
    u16* __restrict__ tvh)
{
    __shared__ __align__(16) u16 skh[BN][SKP];
    __shared__ __align__(16) u16 skl[BN][SKP];
    __shared__ __align__(16) u16 svh[VB][SVP];
    __shared__ __align__(16) u16 svl[VB][SVP];

    const int qblk = blockIdx.x;
    const int h = blockIdx.y, b = blockIdx.z;
    const int kv = h / NREP;
    const int tid = threadIdx.x, warp = tid >> 5, lane = tid & 31;
    const int g = lane >> 2, tg = lane & 3;
    const int qw0 = qblk * QM + warp * 16;

    const u16* qbh = qmh + ((size_t)(b * NH + h) * SS) * QKB;
    const u16* qbl = qml + ((size_t)(b * NH + h) * SS) * QKB;
    size_t a0 = (size_t)(qw0 + g) * QKB + tg * 2;
    u32 a_hi[4], a_lo[4];
    a_hi[0] = *(const u32*)(qbh + a0);
    a_hi[1] = *(const u32*)(qbh + a0 + 8 * QKB);
    a_hi[2] = *(const u32*)(qbh + a0 + 8);
    a_hi[3] = *(const u32*)(qbh + a0 + 8 * QKB + 8);
    a_lo[0] = *(const u32*)(qbl + a0);
    a_lo[1] = *(const u32*)(qbl + a0 + 8 * QKB);
    a_lo[2] = *(const u32*)(qbl + a0 + 8);
    a_lo[3] = *(const u32*)(qbl + a0 + 8 * QKB + 8);
    const float* qcb = qc + (size_t)(b * NH + h) * SS + qw0;
    const float c0 = qcb[g], c1 = qcb[g + 8];
    const int qg0 = qw0 + g, qg1 = qg0 + 8;

    float num[4][4];
#pragma unroll
    for (int i = 0; i < 4; i++)
#pragma unroll
        for (int j = 0; j < 4; j++) num[i][j] = 0.f;
    float den0 = 0.f, den1 = 0.f;

    const u16* kbh = kh + ((size_t)(b * NKV + kv) * SS) * QKB;
    const u16* kbl = kl + ((size_t)(b * NKV + kv) * SS) * QKB;
    const u16* vbh = vth + ((size_t)(b * NKV + kv) * VB) * SS;
    const u16* vbl = vtl + ((size_t)(b * NKV + kv) * VB) * SS;

    for (int t0 = 0; t0 <= qblk; t0++) {
        {
            int r = tid & 127;
            const u16* src = ((tid < 128) ? kbh : kbl) + ((size_t)(t0 * BN + r)) * QKB;
            u16 (*dst)[SKP] = (tid < 128) ? skh : skl;
            float4 v0 = ((const float4*)src)[0];
            float4 v1 = ((const float4*)src)[1];
            *(float4*)&dst[r][0] = v0;
            *(float4*)&dst[r][8] = v1;
        }
#pragma unroll
        for (int i = 0; i < 2; i++) {
            int idx = tid + i * 256;
            int row = idx >> 4, c4 = idx & 15;
            *(float4*)&svh[row][c4 * 8] =
                *((const float4*)(vbh + (size_t)row * SS + t0 * BN) + c4);
            *(float4*)&svl[row][c4 * 8] =
                *((const float4*)(vbl + (size_t)row * SS + t0 * BN) + c4);
        }
        __syncthreads();

        const bool diag = (t0 == qblk);
        for (int kc = 0; kc < 8; kc++) {
            float sc[2][4];
#pragma unroll
            for (int hf = 0; hf < 2; hf++) {
                int n8 = kc * 16 + hf * 8;
                u32 bh_[2], bl_[2];
                const u16* kr  = &skh[n8 + g][tg * 2];
                const u16* krl = &skl[n8 + g][tg * 2];
                bh_[0] = *(const u32*)kr;        bh_[1] = *(const u32*)(kr + 8);
                bl_[0] = *(const u32*)krl;       bl_[1] = *(const u32*)(krl + 8);
                float cc[4] = {0.f, 0.f, 0.f, 0.f};
                mma16816(cc, a_hi, bh_);
                mma16816(cc, a_hi, bl_);
                mma16816(cc, a_lo, bh_);
                sc[hf][0] = cc[0]; sc[hf][1] = cc[1];
                sc[hf][2] = cc[2]; sc[hf][3] = cc[3];
            }
            u32 Ah[4], Al[4];
#pragma unroll
            for (int hf = 0; hf < 2; hf++) {
                int kb = t0 * BN + kc * 16 + hf * 8 + tg * 2;
                float p0 = __expf(sc[hf][0] + c0);
                float p1 = __expf(sc[hf][1] + c0);
                float p2 = __expf(sc[hf][2] + c1);
                float p3 = __expf(sc[hf][3] + c1);
                if (diag) {
                    if (kb     > qg0) p0 = 0.f;
                    if (kb + 1 > qg0) p1 = 0.f;
                    if (kb     > qg1) p2 = 0.f;
                    if (kb + 1 > qg1) p3 = 0.f;
                }
                den0 += p0 + p1;
                den1 += p2 + p3;
                float h0, l0, h1, l1, h2, l2, h3, l3;
                bsplit(p0, h0, l0); bsplit(p1, h1, l1);
                bsplit(p2, h2, l2); bsplit(p3, h3, l3);
                Ah[hf * 2]     = packbf2(h0, h1);
                Ah[hf * 2 + 1] = packbf2(h2, h3);
                Al[hf * 2]     = packbf2(l0, l1);
                Al[hf * 2 + 1] = packbf2(l2, l3);
            }
#pragma unroll
            for (int vt = 0; vt < 4; vt++) {
                u32 bvh[2], bvl[2];
                const u16* vr  = &svh[vt * 8 + g][kc * 16 + tg * 2];
                const u16* vrl = &svl[vt * 8 + g][kc * 16 + tg * 2];
                bvh[0] = *(const u32*)vr;   bvh[1] = *(const u32*)(vr + 8);
                bvl[0] = *(const u32*)vrl;  bvl[1] = *(const u32*)(vrl + 8);
                mma16816(num[vt], Ah, bvh);
                mma16816(num[vt], Ah, bvl);
                mma16816(num[vt], Al, bvh);
            }
        }
        __syncthreads();
    }

    den0 += __shfl_xor_sync(0xffffffffu, den0, 1);
    den0 += __shfl_xor_sync(0xffffffffu, den0, 2);
    den1 += __shfl_xor_sync(0xffffffffu, den1, 1);
    den1 += __shfl_xor_sync(0xffffffffu, den1, 2);
    const float s0f = 2.f / den0, s1f = 2.f / den1;

#pragma unroll
    for (int vt = 0; vt < 4; vt++) {
        int vd = vt * 8 + tg * 2;
        size_t i0 = ((size_t)(b * SS + qg0) * NH + h) * VB + vd;
        size_t i1 = ((size_t)(b * SS + qg1) * NH + h) * VB + vd;
        u32 t0p = packh2(fmaf(s0f, num[vt][0], -1.f), fmaf(s0f, num[vt][1], -1.f));
        u32 t1p = packh2(fmaf(s1f, num[vt][2], -1.f), fmaf(s1f, num[vt][3], -1.f));
        *(u32*)&tvh[i0] = t0p;
        *(u32*)&tvh[i1] = t1p;
    }
}

// ---------------------------------------------------------------------------
extern "C" void kernel_launch(void* const* d_in, const int* in_sizes, int n_in,
                              void* d_out, int out_size)
{
    const float* hs = (const float*)d_in[0];
    const float* Wq = (const float*)d_in[1];
    const float* Wk = (const float*)d_in[2];
    const float* Wv = (const float*)d_in[3];
    const float* Wo = (const float*)d_in[4];
    const float* e0 = (const float*)d_in[5];
    const float* e1 = (const float*)d_in[6];
    float* out = (float*)d_out;

    u16 *hsh, *hsl, *wth, *wtl, *woth, *wotl, *tvh;
    u16 *qmh, *qml, *kh_, *kl_, *vth, *vtl;
    float *qkv, *qcp, *cvec;
    cudaGetSymbolAddress((void**)&hsh,  g_hsh);
    cudaGetSymbolAddress((void**)&hsl,  g_hsl);
    cudaGetSymbolAddress((void**)&wth,  g_wth);
    cudaGetSymbolAddress((void**)&wtl,  g_wtl);
    cudaGetSymbolAddress((void**)&woth, g_woth);
    cudaGetSymbolAddress((void**)&wotl, g_wotl);
    cudaGetSymbolAddress((void**)&qkv,  g_qkv);
    cudaGetSymbolAddress((void**)&tvh,  g_tvh);
    cudaGetSymbolAddress((void**)&cvec, g_cvec);
    cudaGetSymbolAddress((void**)&qcp,  g_qc);
    cudaGetSymbolAddress((void**)&qmh,  g_qmh);
    cudaGetSymbolAddress((void**)&qml,  g_qml);
    cudaGetSymbolAddress((void**)&kh_,  g_kh);
    cudaGetSymbolAddress((void**)&kl_,  g_kl);
    cudaGetSymbolAddress((void**)&vth,  g_vth);
    cudaGetSymbolAddress((void**)&vtl,  g_vtl);

    convert_split_kernel<<<(MROWS * DD / 8 + 255) / 256, 256>>>(hs, hsh, hsl, MROWS * DD);
    transpose_split_kernel<0><<<dim3(256 / 32, DD / 32), 256>>>(
        Wq, DD, 256, wth, wtl, DD, 0, nullptr, nullptr);
    transpose_split_kernel<0><<<dim3(64 / 32,  DD / 32), 256>>>(
        Wk, DD, 64,  wth, wtl, DD, 256, nullptr, nullptr);
    transpose_split_kernel<0><<<dim3(128 / 32, DD / 32), 256>>>(
        Wv, DD, 128, wth, wtl, DD, 320, nullptr, nullptr);
    transpose_split_kernel<1><<<dim3(DD / 32,  KO / 32), 256>>>(
        Wo, KO, DD,  woth, wotl, KO, 0, e0, e1);
    cvec_kernel<<<DD / 256, 256>>>(Wo, e0, e1, cvec);

    // Fused QKV projection (bf16 tensor cores, sigmoid epilogue)
    bgemm_kernel<<<dim3(NQKV / 64, MROWS / 128), 256>>>(
        hsh, hsl, wth, wtl, qkv, MROWS, NQKV, DD);

    convqk_kernel<true ><<<(MROWS * NH  + 127) / 128, 128>>>(qkv, NQKV, 0,   qmh, qml, qcp, NH);
    convqk_kernel<false><<<(MROWS * NKV + 127) / 128, 128>>>(qkv, NQKV, 256, kh_, kl_, nullptr, NKV);
    convv_kernel<<<dim3(SS / 64, NKV, BB), 256>>>(qkv, vth, vtl);

    // Attention emits t = 2vh-1 (fp16)
    rosa_attn_mma<<<dim3(SS / QM, NH, BB), 256>>>(qmh, qml, qcp, kh_, kl_, vth, vtl, tvh);

    // O-projection: 2-MMA fp16 GEMM + cvec epilogue
    bgemm_o<<<dim3(DD / 64, MROWS / 128), 256>>>(tvh, woth, wotl, cvec, out, MROWS, DD, KO);
}